// round 2
// baseline (speedup 1.0000x reference)
#include <cuda_runtime.h>
#include <math.h>

// ---------------------------------------------------------------------------
// Problem constants
// ---------------------------------------------------------------------------
namespace {
constexpr int kB = 2, kS = 1024, kE = 1024, kH = 16, kD = 64, kF = 4096, kV = 32000;
constexpr int kBS  = kB * kS;   // 2048 tokens
constexpr int kBH  = kB * kH;   // 32 (b,h) pairs
constexpr int kQKV = 3 * kE;    // 3072 fused qkv cols
}

// ---------------------------------------------------------------------------
// Device scratch (allocation-free: static __device__ globals)
// ---------------------------------------------------------------------------
__device__ float g_emb [kBS * kE];
__device__ float g_hbuf[kBS * kE];
__device__ float g_qkv [kBS * kQKV];
__device__ float g_q   [kBH * kS * kD];
__device__ float g_kk  [kBH * kS * kD];
__device__ float g_vv  [kBH * kS * kD];
__device__ float g_sc  [(size_t)kBH * kS * kS];   // 128 MB attention scores
__device__ float g_o   [kBH * kS * kD];
__device__ float g_o2  [kBS * kE];
__device__ float g_u   [kBS * kF];
__device__ float g_g   [kBS * kF];
__device__ float g_wt  [kE * kQKV];               // transposed fused qkv weights
__device__ float g_ct  [kS * kD];                 // rope cos
__device__ float g_st  [kS * kD];                 // rope sin (sign folded)

// ---------------------------------------------------------------------------
// Generic tiled fp32 GEMM.
//   C[M,N] = alpha * A@B (+ C if ACCUM) (+ bias[n] if BIAS)
//   A row-major [M,K] lda;  B row-major [K,N] ldb  (or [N,K] if TRB -> C=A@B^T)
//   Batched via blockIdx.z with element strides sA/sB/sC.
//   CAUSAL: skip blocks entirely above the diagonal (scores GEMM).
// Requires: M%BM==0, N%BN==0, K%BK==0, all leading dims %4==0.
// ---------------------------------------------------------------------------
template<int BM,int BN,int BK,int TM,int TN,bool TRB,bool ACCUM,bool BIAS,bool CAUSAL>
__global__ void __launch_bounds__((BM/TM)*(BN/TN))
gemm_k(const float* __restrict__ A, int lda, long long sA,
       const float* __restrict__ B, int ldb, long long sB,
       float* __restrict__ C, int ldc, long long sC,
       const float* __restrict__ bias, float alpha, int K)
{
    constexpr int THREADS = (BM/TM)*(BN/TN);
    const int bx = blockIdx.x, by = blockIdx.y, bz = blockIdx.z;
    if (CAUSAL && bx * BN > by * BM + BM - 1) return;   // fully-masked tile

    A += (long long)bz * sA + (long long)by * BM * lda;
    C += (long long)bz * sC + (long long)by * BM * ldc + bx * BN;
    const float* Bb = B + (long long)bz * sB
                        + (TRB ? (long long)bx * BN * ldb : (long long)bx * BN);

    __shared__ float As[BK][BM];
    __shared__ float Bs[BK][BN];

    const int tid = threadIdx.x;
    const int tx  = tid % (BN / TN);
    const int ty  = tid / (BN / TN);

    float acc[TM][TN];
#pragma unroll
    for (int i = 0; i < TM; i++)
#pragma unroll
        for (int j = 0; j < TN; j++) acc[i][j] = 0.f;

    for (int kt = 0; kt < K; kt += BK) {
        // ---- A tile: BM x BK, transposed into As[k][m] ----
#pragma unroll
        for (int i = tid; i < BM * BK / 4; i += THREADS) {
            int m  = i / (BK / 4);
            int k4 = (i % (BK / 4)) * 4;
            float4 v = *reinterpret_cast<const float4*>(&A[(long long)m * lda + kt + k4]);
            As[k4 + 0][m] = v.x; As[k4 + 1][m] = v.y;
            As[k4 + 2][m] = v.z; As[k4 + 3][m] = v.w;
        }
        // ---- B tile ----
        if (!TRB) {
#pragma unroll
            for (int i = tid; i < BK * BN / 4; i += THREADS) {
                int k  = i / (BN / 4);
                int n4 = (i % (BN / 4)) * 4;
                *reinterpret_cast<float4*>(&Bs[k][n4]) =
                    *reinterpret_cast<const float4*>(&Bb[(long long)(kt + k) * ldb + n4]);
            }
        } else {
#pragma unroll
            for (int i = tid; i < BN * BK / 4; i += THREADS) {
                int n  = i / (BK / 4);
                int k4 = (i % (BK / 4)) * 4;
                float4 v = *reinterpret_cast<const float4*>(&Bb[(long long)n * ldb + kt + k4]);
                Bs[k4 + 0][n] = v.x; Bs[k4 + 1][n] = v.y;
                Bs[k4 + 2][n] = v.z; Bs[k4 + 3][n] = v.w;
            }
        }
        __syncthreads();

#pragma unroll
        for (int kk = 0; kk < BK; kk++) {
            float ra[TM], rb[TN];
#pragma unroll
            for (int i = 0; i < TM; i++) ra[i] = As[kk][ty * TM + i];
#pragma unroll
            for (int j = 0; j < TN; j++) rb[j] = Bs[kk][tx * TN + j];
#pragma unroll
            for (int i = 0; i < TM; i++)
#pragma unroll
                for (int j = 0; j < TN; j++) acc[i][j] += ra[i] * rb[j];
        }
        __syncthreads();
    }

#pragma unroll
    for (int i = 0; i < TM; i++) {
#pragma unroll
        for (int j = 0; j < TN; j++) {
            long long idx = (long long)(ty * TM + i) * ldc + tx * TN + j;
            float v = alpha * acc[i][j];
            if (BIAS)  v += bias[bx * BN + tx * TN + j];
            if (ACCUM) v += C[idx];
            C[idx] = v;
        }
    }
}

// ---------------------------------------------------------------------------
// Elementwise / helper kernels
// ---------------------------------------------------------------------------
__global__ void embed_k(const int* __restrict__ tok, const float* __restrict__ tab,
                        float* __restrict__ out)
{
    int idx = blockIdx.x * blockDim.x + threadIdx.x;   // kBS*kE threads
    int row = idx >> 10;      // /1024
    int e   = idx & 1023;
    out[idx] = tab[(size_t)tok[row] * kE + e];
}

__global__ void costab_k(float* __restrict__ ct, float* __restrict__ st)
{
    int idx = blockIdx.x * blockDim.x + threadIdx.x;   // kS*kD
    int s = idx / kD, i = idx % kD;
    float theta = powf(10000.f, (-2.f / (float)kD) * (float)(i & 31));
    float a = (float)s * theta;
    ct[idx] = cosf(a);
    st[idx] = sinf(a) * (i < kD / 2 ? -1.f : 1.f);
}

// fuse per-layer Wq/Wk/Wv [H,E,D] -> Wt [E, 3*H*D]
__global__ void wt_k(const float* __restrict__ wq, const float* __restrict__ wk,
                     const float* __restrict__ wv, float* __restrict__ wt)
{
    int idx = blockIdx.x * blockDim.x + threadIdx.x;   // kE*kQKV
    int e = idx / kQKV, c = idx % kQKV;
    int seg = c >> 10, cc = c & 1023;
    int h = cc >> 6, k = cc & 63;
    const float* w = (seg == 0) ? wq : (seg == 1) ? wk : wv;
    wt[idx] = w[((size_t)h * kE + e) * kD + k];
}

// qkv [BS, 3072] -> rope(q),rope(k),v in [B,H,S,D]
__global__ void rope_k(const float* __restrict__ qkv,
                       const float* __restrict__ ct, const float* __restrict__ st,
                       float* __restrict__ q, float* __restrict__ k, float* __restrict__ v)
{
    int idx = blockIdx.x * blockDim.x + threadIdx.x;   // kBS*kQKV
    int row = idx / kQKV, c = idx % kQKV;
    int b = row >> 10, s = row & 1023;
    int seg = c >> 10, cc = c & 1023;
    int h = cc >> 6, i = cc & 63;
    float x = qkv[idx];
    size_t dst = ((size_t)(b * kH + h) * kS + s) * kD + i;
    if (seg == 2) { v[dst] = x; return; }
    float sw  = qkv[(size_t)row * kQKV + (seg << 10) + (h << 6) + ((i + 32) & 63)];
    float val = ct[(s << 6) + i] * x + st[(s << 6) + i] * sw;
    (seg == 0 ? q : k)[dst] = val;
}

// causal softmax over scores rows; writes 0 beyond the diagonal
__global__ void softmax_k(float* __restrict__ sc)
{
    const int r = blockIdx.x;                 // kBH*kS rows
    const int s = r & (kS - 1);
    float* row = sc + (size_t)r * kS;
    const int n = s + 1;
    __shared__ float red[256];
    const int t = threadIdx.x;

    float m = -INFINITY;
    for (int i = t; i < n; i += 256) m = fmaxf(m, row[i]);
    red[t] = m; __syncthreads();
    for (int o = 128; o > 0; o >>= 1) {
        if (t < o) red[t] = fmaxf(red[t], red[t + o]);
        __syncthreads();
    }
    m = red[0]; __syncthreads();

    float sum = 0.f;
    for (int i = t; i < n; i += 256) { float e = expf(row[i] - m); row[i] = e; sum += e; }
    red[t] = sum; __syncthreads();
    for (int o = 128; o > 0; o >>= 1) {
        if (t < o) red[t] += red[t + o];
        __syncthreads();
    }
    float inv = 1.f / red[0];
    for (int i = t; i < n; i += 256) row[i] *= inv;
    for (int i = n + t; i < kS; i += 256) row[i] = 0.f;
}

// o [B,H,S,D] -> o2 [B,S,H*D]
__global__ void oresh_k(const float* __restrict__ o, float* __restrict__ o2)
{
    int idx = blockIdx.x * blockDim.x + threadIdx.x;   // kBH*kS*kD
    int bh  = idx / (kS * kD);
    int rem = idx % (kS * kD);
    int s = rem >> 6, d = rem & 63;
    int b = bh / kH, h = bh % kH;
    o2[((size_t)(b * kS + s) << 10) + (h << 6) + d] = o[idx];
}

__global__ void rmsnorm_k(const float* __restrict__ x, const float* __restrict__ w,
                          float* __restrict__ y)
{
    const int r = blockIdx.x;
    const float* xr = x + (size_t)r * kE;
    float* yr = y + (size_t)r * kE;
    __shared__ float red[256];
    const int t = threadIdx.x;
    float sum = 0.f;
    for (int i = t; i < kE; i += 256) { float v = xr[i]; sum += v * v; }
    red[t] = sum; __syncthreads();
    for (int o = 128; o > 0; o >>= 1) {
        if (t < o) red[t] += red[t + o];
        __syncthreads();
    }
    float rs = rsqrtf(red[0] / (float)kE + 1.1920929e-7f);
    for (int i = t; i < kE; i += 256) yr[i] = xr[i] * rs * w[i];
}

__global__ void elumul_k(float* __restrict__ u, const float* __restrict__ g)
{
    int i = blockIdx.x * blockDim.x + threadIdx.x;     // kBS*kF
    float gv = g[i];
    float e = gv > 0.f ? gv : expm1f(gv);
    u[i] *= e;
}

// ---------------------------------------------------------------------------
// Host launcher
// ---------------------------------------------------------------------------
extern "C" void kernel_launch(void* const* d_in, const int* in_sizes, int n_in,
                              void* d_out, int out_size)
{
    (void)in_sizes; (void)n_in; (void)out_size;
    const int*   tokens = (const int*)  d_in[0];
    const float* table  = (const float*)d_in[1];
    const float* Wq     = (const float*)d_in[2];
    const float* Wk     = (const float*)d_in[3];
    const float* Wv     = (const float*)d_in[4];
    const float* Wproj  = (const float*)d_in[5];
    const float* normw  = (const float*)d_in[6];
    const float* Wup    = (const float*)d_in[7];
    const float* Wgate  = (const float*)d_in[8];
    const float* Wdown  = (const float*)d_in[9];
    const float* predW  = (const float*)d_in[10];
    const float* predB  = (const float*)d_in[11];
    float* logits = (float*)d_out;

    float *emb, *hbuf, *qkv, *q, *kk, *vv, *sc, *o, *o2, *u, *g, *wt, *ct, *st;
    cudaGetSymbolAddress((void**)&emb,  g_emb);
    cudaGetSymbolAddress((void**)&hbuf, g_hbuf);
    cudaGetSymbolAddress((void**)&qkv,  g_qkv);
    cudaGetSymbolAddress((void**)&q,    g_q);
    cudaGetSymbolAddress((void**)&kk,   g_kk);
    cudaGetSymbolAddress((void**)&vv,   g_vv);
    cudaGetSymbolAddress((void**)&sc,   g_sc);
    cudaGetSymbolAddress((void**)&o,    g_o);
    cudaGetSymbolAddress((void**)&o2,   g_o2);
    cudaGetSymbolAddress((void**)&u,    g_u);
    cudaGetSymbolAddress((void**)&g,    g_g);
    cudaGetSymbolAddress((void**)&wt,   g_wt);
    cudaGetSymbolAddress((void**)&ct,   g_ct);
    cudaGetSymbolAddress((void**)&st,   g_st);

    const float inv_sqrt = 0.125f;   // 1/sqrt(64)

    embed_k <<<kBS * kE / 256, 256>>>(tokens, table, emb);
    costab_k<<<kS * kD / 256, 256>>>(ct, st);

    for (int l = 0; l < 4; l++) {
        const float* wq = Wq    + (size_t)l * kH * kE * kD;
        const float* wk = Wk    + (size_t)l * kH * kE * kD;
        const float* wv = Wv    + (size_t)l * kH * kE * kD;
        const float* wp = Wproj + (size_t)l * kE * kE;
        const float* nw = normw + (size_t)l * kE;
        const float* wu = Wup   + (size_t)l * kE * kF;
        const float* wg = Wgate + (size_t)l * kE * kF;
        const float* wd = Wdown + (size_t)l * kF * kE;

        // fused QKV weight transpose + one big GEMM  [2048,1024]x[1024,3072]
        wt_k<<<kE * kQKV / 256, 256>>>(wq, wk, wv, wt);
        gemm_k<128,128,16,8,8,false,false,false,false>
            <<<dim3(kQKV/128, kBS/128), 256>>>(emb, kE, 0, wt, kQKV, 0,
                                               qkv, kQKV, 0, nullptr, 1.f, kE);
        rope_k<<<kBS * kQKV / 256, 256>>>(qkv, ct, st, q, kk, vv);

        // scores = q @ k^T * inv_sqrt   (batched over (b,h), causal block-skip)
        gemm_k<128,128,16,8,8,true,false,false,true>
            <<<dim3(kS/128, kS/128, kBH), 256>>>(q, kD, (long long)kS*kD,
                                                 kk, kD, (long long)kS*kD,
                                                 sc, kS, (long long)kS*kS,
                                                 nullptr, inv_sqrt, kD);
        softmax_k<<<kBH * kS, 256>>>(sc);

        // o = attn @ v   [1024,1024]x[1024,64] per (b,h)
        gemm_k<128,64,16,8,4,false,false,false,false>
            <<<dim3(1, kS/128, kBH), 256>>>(sc, kS, (long long)kS*kS,
                                            vv, kD, (long long)kS*kD,
                                            o,  kD, (long long)kS*kD,
                                            nullptr, 1.f, kS);
        oresh_k<<<kBH * kS * kD / 256, 256>>>(o, o2);

        // emb += o2 @ Wproj
        gemm_k<128,128,16,8,8,false,true,false,false>
            <<<dim3(kE/128, kBS/128), 256>>>(o2, kE, 0, wp, kE, 0,
                                             emb, kE, 0, nullptr, 1.f, kE);

        // MLP
        rmsnorm_k<<<kBS, 256>>>(emb, nw, hbuf);
        gemm_k<128,128,16,8,8,false,false,false,false>
            <<<dim3(kF/128, kBS/128), 256>>>(hbuf, kE, 0, wu, kF, 0,
                                             u, kF, 0, nullptr, 1.f, kE);
        gemm_k<128,128,16,8,8,false,false,false,false>
            <<<dim3(kF/128, kBS/128), 256>>>(hbuf, kE, 0, wg, kF, 0,
                                             g, kF, 0, nullptr, 1.f, kE);
        elumul_k<<<kBS * kF / 256, 256>>>(u, g);
        gemm_k<128,128,16,8,8,false,true,false,false>
            <<<dim3(kE/128, kBS/128), 256>>>(u, kF, 0, wd, kE, 0,
                                             emb, kE, 0, nullptr, 1.f, kF);
    }

    // logits = emb @ pred_W + pred_b   [2048,1024]x[1024,32000]
    gemm_k<128,128,16,8,8,false,false,true,false>
        <<<dim3(kV/128, kBS/128), 256>>>(emb, kE, 0, predW, kV, 0,
                                         logits, kV, 0, predB, 1.f, kE);
}

// round 4
// speedup vs baseline: 2.1431x; 2.1431x over previous
#include <cuda_runtime.h>
#include <cuda_fp16.h>
#include <math.h>
#include <stdint.h>

namespace {
constexpr int kB = 2, kS = 1024, kE = 1024, kH = 16, kD = 64, kF = 4096, kV = 32000;
constexpr int kBS = kB * kS, kBH = kB * kH, kQKV = 3 * kE;
}

// ------------------------- device scratch -------------------------
__device__ float  g_emb [kBS * kE];
__device__ float  g_qkv [kBS * kQKV];
__device__ float  g_sc  [(size_t)kBH * kS * kS];
__device__ float  g_o   [kBH * kS * kD];
__device__ float  g_u   [kBS * kF];
__device__ float  g_g   [kBS * kF];
__device__ float  g_ct  [kS * kD];
__device__ float  g_st  [kS * kD];

__device__ __half g_eh[kBS*kE], g_el[kBS*kE];
__device__ __half g_wqkvh[kQKV*kE], g_wqkvl[kQKV*kE];
__device__ __half g_qh[kBH*kS*kD], g_ql[kBH*kS*kD];
__device__ __half g_kh[kBH*kS*kD], g_kl[kBH*kS*kD];
__device__ __half g_vth[kBH*kD*kS], g_vtl[kBH*kD*kS];
__device__ __half g_ph[(size_t)kBH*kS*kS], g_pl[(size_t)kBH*kS*kS];
__device__ __half g_o2h[kBS*kE], g_o2l[kBS*kE];
__device__ __half g_wph[kE*kE],  g_wpl[kE*kE];
__device__ __half g_wuh[kF*kE],  g_wul[kF*kE];
__device__ __half g_wgh[kF*kE],  g_wgl[kF*kE];
__device__ __half g_wdh[kE*kF],  g_wdl[kE*kF];
__device__ __half g_hh[kBS*kE],  g_hl[kBS*kE];
__device__ __half g_uh[kBS*kF],  g_ul[kBS*kF];
__device__ __half g_pwh[(size_t)kV*kE], g_pwl[(size_t)kV*kE];

// ------------------------- PTX helpers (compute_80-class only) -------------------------
__device__ __forceinline__ uint32_t smem_u32(const void* p) {
    uint32_t a;
    asm("{ .reg .u64 t; cvta.to.shared.u64 t, %1; cvt.u32.u64 %0, t; }" : "=r"(a) : "l"(p));
    return a;
}
__device__ __forceinline__ void cpasync16(uint32_t dst, const void* src) {
    asm volatile("cp.async.cg.shared.global [%0], [%1], 16;" :: "r"(dst), "l"(src));
}
#define CP_COMMIT() asm volatile("cp.async.commit_group;" ::: "memory")
#define CP_WAIT1()  asm volatile("cp.async.wait_group 1;" ::: "memory")

__device__ __forceinline__ void ldsm4(uint32_t* r, uint32_t addr) {
    asm volatile("ldmatrix.sync.aligned.m8n8.x4.shared.b16 {%0,%1,%2,%3}, [%4];"
        : "=r"(r[0]), "=r"(r[1]), "=r"(r[2]), "=r"(r[3]) : "r"(addr));
}
__device__ __forceinline__ void hmma(float* c, const uint32_t* a, const uint32_t* b) {
    asm volatile("mma.sync.aligned.m16n8k16.row.col.f32.f16.f16.f32 "
        "{%0,%1,%2,%3}, {%4,%5,%6,%7}, {%8,%9}, {%0,%1,%2,%3};"
        : "+f"(c[0]), "+f"(c[1]), "+f"(c[2]), "+f"(c[3])
        : "r"(a[0]), "r"(a[1]), "r"(a[2]), "r"(a[3]), "r"(b[0]), "r"(b[1]));
}
__device__ __forceinline__ void split2(float v, __half* h, __half* l) {
    __half hi = __float2half(v);
    *h = hi;
    *l = __float2half((v - __half2float(hi)) * 1024.f);
}

// stage one ROWS x 32 fp16 tile into 80B-padded smem rows via cp.async
template<int ROWS>
__device__ __forceinline__ void stage_cp(uint32_t dst, const __half* __restrict__ src,
                                         long long ld, int k0, int tid)
{
#pragma unroll
    for (int it = 0; it < ROWS * 4 / 256; it++) {
        int i = it * 256 + tid;
        int r = i >> 2, c = i & 3;
        cpasync16(dst + r * 80 + c * 16, src + (long long)r * ld + k0 + c * 8);
    }
}

// ------------------------- HMMA GEMM -------------------------
// C[M,N] = alpha * (A @ B^T) (+bias[n]) (+C). A:[M,K] hi/lo fp16 K-major,
// B:[N,K] hi/lo fp16 K-major. BM=128. lo is pre-scaled by 1024.
// CAUSAL: skip tiles above diagonal. CAUSK: clamp K at (by+1)*128.
template<int BN, bool ACCUM, bool BIAS, bool CAUSAL, bool CAUSK>
__global__ void __launch_bounds__(256, 1)
tgemm_k(const __half* __restrict__ Ah, const __half* __restrict__ Al, int lda, long long sA,
        const __half* __restrict__ Bh, const __half* __restrict__ Bl, int ldb, long long sB,
        float* __restrict__ C, int ldc, long long sC,
        const float* __restrict__ bias, float alpha, int K)
{
    constexpr int BM = 128, BK = 32, NST = 3;
    constexpr int WM = (BN == 128) ? 2 : 4;     // warp grid (M x N), 8 warps
    constexpr int WN = 8 / WM;
    constexpr int MT = BM / (WM * 16);          // m16 tiles per warp
    constexpr int NT = BN / (WN * 8);           // n8 tiles per warp
    constexpr int TILEA = BM * 80;
    constexpr int TILEB = BN * 80;
    constexpr int STAGE = 2 * TILEA + 2 * TILEB;

    const int bx = blockIdx.x, by = blockIdx.y, bz = blockIdx.z;
    if (CAUSAL && bx * BN > by * BM + BM - 1) return;
    int Ktot = K;
    if (CAUSK) { int km = (by + 1) * BM; if (km < Ktot) Ktot = km; }
    const int NC = Ktot / BK;

    extern __shared__ char sm[];
    const uint32_t sb = smem_u32(sm);
    const int tid = threadIdx.x, lane = tid & 31, wid = tid >> 5;
    const int m0 = (wid / WN) * MT * 16;
    const int n0 = (wid % WN) * NT * 8;

    const __half* pAh = Ah + bz * sA + (long long)by * BM * lda;
    const __half* pAl = Al + bz * sA + (long long)by * BM * lda;
    const __half* pBh = Bh + bz * sB + (long long)bx * BN * ldb;
    const __half* pBl = Bl + bz * sB + (long long)bx * BN * ldb;

    float acc1[MT][NT][4];
    float acc2[MT][NT][4];
#pragma unroll
    for (int mt = 0; mt < MT; mt++)
#pragma unroll
        for (int nt = 0; nt < NT; nt++)
#pragma unroll
            for (int i = 0; i < 4; i++) { acc1[mt][nt][i] = 0.f; acc2[mt][nt][i] = 0.f; }

    auto stage_all = [&](int buf, int k0) {
        uint32_t s0 = sb + (uint32_t)buf * STAGE;
        stage_cp<BM>(s0,                    pAh, lda, k0, tid);
        stage_cp<BM>(s0 + TILEA,            pAl, lda, k0, tid);
        stage_cp<BN>(s0 + 2*TILEA,          pBh, ldb, k0, tid);
        stage_cp<BN>(s0 + 2*TILEA + TILEB,  pBl, ldb, k0, tid);
    };

    for (int s = 0; s < NST - 1 && s < NC; s++) { stage_all(s, s * BK); CP_COMMIT(); }

    for (int i = 0; i < NC; i++) {
        CP_WAIT1();
        __syncthreads();
        if (i + NST - 1 < NC) stage_all((i + NST - 1) % NST, (i + NST - 1) * BK);
        CP_COMMIT();

        const uint32_t s0 = sb + (uint32_t)(i % NST) * STAGE;
        const uint32_t aH = s0, aL = s0 + TILEA;
        const uint32_t bH = s0 + 2*TILEA, bL = s0 + 2*TILEA + TILEB;

#pragma unroll
        for (int kk = 0; kk < 2; kk++) {
            const int kc = kk * 2;   // 16B-chunk index of k16 block
            uint32_t a[MT][4], bhf[NT][2], blf[NT][2];

            // B hi/lo fragments (two n8 tiles per ldmatrix.x4)
#pragma unroll
            for (int nt = 0; nt < NT; nt += 2) {
                const int g = lane >> 3;
                const uint32_t off =
                    (uint32_t)(n0 + nt * 8 + ((g >> 1) << 3) + (lane & 7)) * 80
                    + (uint32_t)(kc + (g & 1)) * 16;
                uint32_t r[4];
                ldsm4(r, bH + off);
                bhf[nt][0] = r[0]; bhf[nt][1] = r[1];
                bhf[nt+1][0] = r[2]; bhf[nt+1][1] = r[3];
                ldsm4(r, bL + off);
                blf[nt][0] = r[0]; blf[nt][1] = r[1];
                blf[nt+1][0] = r[2]; blf[nt+1][1] = r[3];
            }

            // A-hi fragments, then acc1 += Ah*Bh, acc2 += Ah*Bl
#pragma unroll
            for (int mt = 0; mt < MT; mt++) {
                const uint32_t off =
                    (uint32_t)(m0 + mt * 16 + (lane & 15)) * 80
                    + (uint32_t)(kc + (lane >> 4)) * 16;
                ldsm4(a[mt], aH + off);
            }
#pragma unroll
            for (int mt = 0; mt < MT; mt++)
#pragma unroll
                for (int nt = 0; nt < NT; nt++) {
                    hmma(acc1[mt][nt], a[mt], bhf[nt]);
                    hmma(acc2[mt][nt], a[mt], blf[nt]);
                }

            // A-lo fragments (reuse regs), acc2 += Al*Bh
#pragma unroll
            for (int mt = 0; mt < MT; mt++) {
                const uint32_t off =
                    (uint32_t)(m0 + mt * 16 + (lane & 15)) * 80
                    + (uint32_t)(kc + (lane >> 4)) * 16;
                ldsm4(a[mt], aL + off);
            }
#pragma unroll
            for (int mt = 0; mt < MT; mt++)
#pragma unroll
                for (int nt = 0; nt < NT; nt++)
                    hmma(acc2[mt][nt], a[mt], bhf[nt]);
        }
    }

    // ---- epilogue: direct register -> global ----
    const float inv = 1.f / 1024.f;
    float* Cp = C + bz * sC;
#pragma unroll
    for (int mt = 0; mt < MT; mt++) {
#pragma unroll
        for (int nt = 0; nt < NT; nt++) {
            const int row = by * BM + m0 + mt * 16 + (lane >> 2);
            const int col = bx * BN + n0 + nt * 8 + ((lane & 3) << 1);
#pragma unroll
            for (int h = 0; h < 2; h++) {
                const int r = row + h * 8;
                float v0 = (acc1[mt][nt][2*h]   + acc2[mt][nt][2*h]   * inv) * alpha;
                float v1 = (acc1[mt][nt][2*h+1] + acc2[mt][nt][2*h+1] * inv) * alpha;
                if (BIAS) { v0 += bias[col]; v1 += bias[col + 1]; }
                float2* p = reinterpret_cast<float2*>(Cp + (long long)r * ldc + col);
                if (ACCUM) { float2 o = *p; v0 += o.x; v1 += o.y; }
                *p = make_float2(v0, v1);
            }
        }
    }
}

// ------------------------- elementwise kernels -------------------------
__global__ void embed_k(const int* __restrict__ tok, const float* __restrict__ tab,
                        float* __restrict__ out, __half* __restrict__ eh, __half* __restrict__ el)
{
    int idx = blockIdx.x * blockDim.x + threadIdx.x;
    float v = tab[(size_t)tok[idx >> 10] * kE + (idx & 1023)];
    out[idx] = v; split2(v, eh + idx, el + idx);
}

__global__ void costab_k(float* __restrict__ ct, float* __restrict__ st)
{
    int idx = blockIdx.x * blockDim.x + threadIdx.x;
    int s = idx / kD, i = idx % kD;
    float theta = powf(10000.f, (-2.f / kD) * (float)(i & 31));
    ct[idx] = cosf((float)s * theta);
    st[idx] = sinf((float)s * theta) * (i < kD/2 ? -1.f : 1.f);
}

__global__ void wqkv_k(const float* __restrict__ wq, const float* __restrict__ wk,
                       const float* __restrict__ wv, __half* __restrict__ h, __half* __restrict__ l)
{
    int idx = blockIdx.x * blockDim.x + threadIdx.x;   // kQKV*kE
    int n = idx / kE, e = idx % kE;
    int seg = n >> 10, hh = (n & 1023) >> 6, k = n & 63;
    const float* w = seg == 0 ? wq : seg == 1 ? wk : wv;
    split2(w[((size_t)hh * kE + e) * kD + k], h + idx, l + idx);
}

__global__ void wtr_k(const float* __restrict__ src, __half* __restrict__ dh,
                      __half* __restrict__ dl, int K, int N)
{
    __shared__ float t[32][33];
    int k0 = blockIdx.y * 32, n0 = blockIdx.x * 32;
    for (int r = threadIdx.y; r < 32; r += 8)
        t[r][threadIdx.x] = src[(size_t)(k0 + r) * N + n0 + threadIdx.x];
    __syncthreads();
    for (int r = threadIdx.y; r < 32; r += 8) {
        size_t o = (size_t)(n0 + r) * K + k0 + threadIdx.x;
        split2(t[threadIdx.x][r], dh + o, dl + o);
    }
}

__global__ void rope_k(const float* __restrict__ qkv, const float* __restrict__ ct,
                       const float* __restrict__ st,
                       __half* __restrict__ qh, __half* __restrict__ ql,
                       __half* __restrict__ kh, __half* __restrict__ kl,
                       __half* __restrict__ vth, __half* __restrict__ vtl)
{
    int idx = blockIdx.x * blockDim.x + threadIdx.x;   // kBS*kQKV
    int row = idx / kQKV, c = idx % kQKV;
    int b = row >> 10, s = row & 1023;
    int seg = c >> 10, h = (c & 1023) >> 6, i = c & 63;
    float x = qkv[idx];
    if (seg == 2) {
        size_t dst = ((size_t)(b * kH + h) * kD + i) * kS + s;
        split2(x, vth + dst, vtl + dst);
        return;
    }
    float sw = qkv[(size_t)row * kQKV + (seg << 10) + (h << 6) + ((i + 32) & 63)];
    float val = ct[(s << 6) + i] * x + st[(s << 6) + i] * sw;
    size_t dst = ((size_t)(b * kH + h) * kS + s) * kD + i;
    if (seg == 0) split2(val, qh + dst, ql + dst);
    else          split2(val, kh + dst, kl + dst);
}

__global__ void softmax_k(float* __restrict__ sc, __half* __restrict__ ph, __half* __restrict__ pl)
{
    const int r = blockIdx.x, s = r & (kS - 1), n = s + 1, t = threadIdx.x;
    float* row = sc + (size_t)r * kS;
    __half* prh = ph + (size_t)r * kS;
    __half* prl = pl + (size_t)r * kS;
    __shared__ float red[256];
    float m = -INFINITY;
    for (int i = t; i < n; i += 256) m = fmaxf(m, row[i]);
    red[t] = m; __syncthreads();
    for (int o = 128; o > 0; o >>= 1) { if (t < o) red[t] = fmaxf(red[t], red[t+o]); __syncthreads(); }
    m = red[0]; __syncthreads();
    float sum = 0.f;
    for (int i = t; i < n; i += 256) { float e = expf(row[i] - m); row[i] = e; sum += e; }
    red[t] = sum; __syncthreads();
    for (int o = 128; o > 0; o >>= 1) { if (t < o) red[t] += red[t+o]; __syncthreads(); }
    float inv = 1.f / red[0];
    for (int i = t; i < n; i += 256) split2(row[i] * inv, prh + i, prl + i);
    for (int i = n + t; i < kS; i += 256) { prh[i] = __float2half(0.f); prl[i] = __float2half(0.f); }
}

__global__ void oresh_k(const float* __restrict__ o, __half* __restrict__ oh, __half* __restrict__ ol)
{
    int idx = blockIdx.x * blockDim.x + threadIdx.x;   // kBH*kS*kD
    int bh = idx / (kS * kD), rem = idx % (kS * kD);
    int s = rem >> 6, d = rem & 63, b = bh / kH, h = bh % kH;
    size_t dst = ((size_t)(b * kS + s) << 10) + (h << 6) + d;
    split2(o[idx], oh + dst, ol + dst);
}

__global__ void split_k(const float* __restrict__ x, __half* __restrict__ h, __half* __restrict__ l)
{
    int i = blockIdx.x * blockDim.x + threadIdx.x;
    split2(x[i], h + i, l + i);
}

__global__ void rmsnorm_k(const float* __restrict__ x, const float* __restrict__ w,
                          __half* __restrict__ yh, __half* __restrict__ yl)
{
    const int r = blockIdx.x, t = threadIdx.x;
    const float* xr = x + (size_t)r * kE;
    __shared__ float red[256];
    float sum = 0.f;
    for (int i = t; i < kE; i += 256) { float v = xr[i]; sum += v * v; }
    red[t] = sum; __syncthreads();
    for (int o = 128; o > 0; o >>= 1) { if (t < o) red[t] += red[t+o]; __syncthreads(); }
    float rs = rsqrtf(red[0] / kE + 1.1920929e-7f);
    for (int i = t; i < kE; i += 256) {
        size_t o = (size_t)r * kE + i;
        split2(xr[i] * rs * w[i], yh + o, yl + o);
    }
}

__global__ void elumul_k(const float* __restrict__ u, const float* __restrict__ g,
                         __half* __restrict__ uh, __half* __restrict__ ul)
{
    int i = blockIdx.x * blockDim.x + threadIdx.x;
    float gv = g[i];
    split2(u[i] * (gv > 0.f ? gv : expm1f(gv)), uh + i, ul + i);
}

// ------------------------- host launcher -------------------------
#define SYM(p, s) cudaGetSymbolAddress((void**)&p, s)

extern "C" void kernel_launch(void* const* d_in, const int* in_sizes, int n_in,
                              void* d_out, int out_size)
{
    (void)in_sizes; (void)n_in; (void)out_size;
    const int*   tokens = (const int*)  d_in[0];
    const float* table = (const float*)d_in[1];
    const float *Wq = (const float*)d_in[2], *Wk = (const float*)d_in[3], *Wv = (const float*)d_in[4];
    const float *Wproj = (const float*)d_in[5], *normw = (const float*)d_in[6];
    const float *Wup = (const float*)d_in[7], *Wgate = (const float*)d_in[8], *Wdown = (const float*)d_in[9];
    const float *predW = (const float*)d_in[10], *predB = (const float*)d_in[11];
    float* logits = (float*)d_out;

    float *emb, *qkv, *sc, *o, *u, *g, *ct, *st;
    __half *eh, *el, *wqkvh, *wqkvl, *qh, *ql, *kh, *kl, *vth, *vtl, *ph, *pl;
    __half *o2h, *o2l, *wph, *wpl, *wuh, *wul, *wgh, *wgl, *wdh, *wdl, *hh, *hl, *uh, *ul, *pwh, *pwl;
    SYM(emb, g_emb); SYM(qkv, g_qkv); SYM(sc, g_sc); SYM(o, g_o); SYM(u, g_u); SYM(g, g_g);
    SYM(ct, g_ct); SYM(st, g_st);
    SYM(eh, g_eh); SYM(el, g_el); SYM(wqkvh, g_wqkvh); SYM(wqkvl, g_wqkvl);
    SYM(qh, g_qh); SYM(ql, g_ql); SYM(kh, g_kh); SYM(kl, g_kl);
    SYM(vth, g_vth); SYM(vtl, g_vtl); SYM(ph, g_ph); SYM(pl, g_pl);
    SYM(o2h, g_o2h); SYM(o2l, g_o2l); SYM(wph, g_wph); SYM(wpl, g_wpl);
    SYM(wuh, g_wuh); SYM(wul, g_wul); SYM(wgh, g_wgh); SYM(wgl, g_wgl);
    SYM(wdh, g_wdh); SYM(wdl, g_wdl); SYM(hh, g_hh); SYM(hl, g_hl);
    SYM(uh, g_uh); SYM(ul, g_ul); SYM(pwh, g_pwh); SYM(pwl, g_pwl);

    const int SM128 = 3 * (2 * 128 * 80 + 2 * 128 * 80);   // 122880
    const int SM64  = 3 * (2 * 128 * 80 + 2 * 64 * 80);    // 92160
    cudaFuncSetAttribute(tgemm_k<128,false,false,false,false>, cudaFuncAttributeMaxDynamicSharedMemorySize, SM128);
    cudaFuncSetAttribute(tgemm_k<128,false,false,true ,false>, cudaFuncAttributeMaxDynamicSharedMemorySize, SM128);
    cudaFuncSetAttribute(tgemm_k<128,true ,false,false,false>, cudaFuncAttributeMaxDynamicSharedMemorySize, SM128);
    cudaFuncSetAttribute(tgemm_k<128,false,true ,false,false>, cudaFuncAttributeMaxDynamicSharedMemorySize, SM128);
    cudaFuncSetAttribute(tgemm_k<64 ,false,false,false,true >, cudaFuncAttributeMaxDynamicSharedMemorySize, SM64);

    embed_k <<<kBS * kE / 256, 256>>>(tokens, table, emb, eh, el);
    costab_k<<<kS * kD / 256, 256>>>(ct, st);

    for (int l = 0; l < 4; l++) {
        const float* wq = Wq    + (size_t)l * kH * kE * kD;
        const float* wk = Wk    + (size_t)l * kH * kE * kD;
        const float* wv = Wv    + (size_t)l * kH * kE * kD;
        const float* wp = Wproj + (size_t)l * kE * kE;
        const float* nw = normw + (size_t)l * kE;
        const float* wu = Wup   + (size_t)l * kE * kF;
        const float* wg = Wgate + (size_t)l * kE * kF;
        const float* wd = Wdown + (size_t)l * kF * kE;

        // QKV: [2048,1024] x [3072,1024]^T
        wqkv_k<<<kQKV * kE / 256, 256>>>(wq, wk, wv, wqkvh, wqkvl);
        tgemm_k<128,false,false,false,false><<<dim3(kQKV/128, kBS/128), 256, SM128>>>(
            eh, el, kE, 0, wqkvh, wqkvl, kE, 0, qkv, kQKV, 0, nullptr, 1.f, kE);
        rope_k<<<kBS * kQKV / 256, 256>>>(qkv, ct, st, qh, ql, kh, kl, vth, vtl);

        // scores = q @ k^T / 8 (causal tile-skip)
        tgemm_k<128,false,false,true,false><<<dim3(kS/128, kS/128, kBH), 256, SM128>>>(
            qh, ql, kD, (long long)kS*kD, kh, kl, kD, (long long)kS*kD,
            sc, kS, (long long)kS*kS, nullptr, 0.125f, kD);
        softmax_k<<<kBH * kS, 256>>>(sc, ph, pl);

        // o = P @ V (causal K-bound)
        tgemm_k<64,false,false,false,true><<<dim3(1, kS/128, kBH), 256, SM64>>>(
            ph, pl, kS, (long long)kS*kS, vth, vtl, kS, (long long)kD*kS,
            o, kD, (long long)kS*kD, nullptr, 1.f, kS);
        oresh_k<<<kBH * kS * kD / 256, 256>>>(o, o2h, o2l);

        // emb += o2 @ Wproj
        wtr_k<<<dim3(kE/32, kE/32), dim3(32,8)>>>(wp, wph, wpl, kE, kE);
        tgemm_k<128,true,false,false,false><<<dim3(kE/128, kBS/128), 256, SM128>>>(
            o2h, o2l, kE, 0, wph, wpl, kE, 0, emb, kE, 0, nullptr, 1.f, kE);

        // MLP
        rmsnorm_k<<<kBS, 256>>>(emb, nw, hh, hl);
        wtr_k<<<dim3(kF/32, kE/32), dim3(32,8)>>>(wu, wuh, wul, kE, kF);
        wtr_k<<<dim3(kF/32, kE/32), dim3(32,8)>>>(wg, wgh, wgl, kE, kF);
        tgemm_k<128,false,false,false,false><<<dim3(kF/128, kBS/128), 256, SM128>>>(
            hh, hl, kE, 0, wuh, wul, kE, 0, u, kF, 0, nullptr, 1.f, kE);
        tgemm_k<128,false,false,false,false><<<dim3(kF/128, kBS/128), 256, SM128>>>(
            hh, hl, kE, 0, wgh, wgl, kE, 0, g, kF, 0, nullptr, 1.f, kE);
        elumul_k<<<kBS * kF / 256, 256>>>(u, g, uh, ul);
        wtr_k<<<dim3(kE/32, kF/32), dim3(32,8)>>>(wd, wdh, wdl, kF, kE);
        tgemm_k<128,true,false,false,false><<<dim3(kE/128, kBS/128), 256, SM128>>>(
            uh, ul, kF, 0, wdh, wdl, kF, 0, emb, kE, 0, nullptr, 1.f, kF);
        split_k<<<kBS * kE / 256, 256>>>(emb, eh, el);
    }

    // logits = emb @ predW + predB : [2048,1024] x [32000,1024]^T
    wtr_k<<<dim3(kV/32, kE/32), dim3(32,8)>>>(predW, pwh, pwl, kE, kV);
    tgemm_k<128,false,true,false,false><<<dim3(kV/128, kBS/128), 256, SM128>>>(
        eh, el, kE, 0, pwh, pwl, kE, 0, logits, kV, 0, predB, 1.f, kE);
}

// round 5
// speedup vs baseline: 2.3813x; 1.1111x over previous
#include <cuda_runtime.h>
#include <cuda_fp16.h>
#include <math.h>
#include <stdint.h>

namespace {
constexpr int kB = 2, kS = 1024, kE = 1024, kH = 16, kD = 64, kF = 4096, kV = 32000;
constexpr int kBS = kB * kS, kBH = kB * kH, kQKV = 3 * kE;
}

// ------------------------- device scratch -------------------------
__device__ float  g_emb [kBS * kE];
__device__ float  g_qkv [kBS * kQKV];
__device__ float  g_sc  [(size_t)kBH * kS * kS];
__device__ float  g_o   [kBH * kS * kD];
__device__ float  g_u   [kBS * kF];
__device__ float  g_g   [kBS * kF];
__device__ float  g_ct  [kS * kD];
__device__ float  g_st  [kS * kD];

__device__ __half g_eh[kBS*kE], g_el[kBS*kE];
__device__ __half g_wqkvh[kQKV*kE], g_wqkvl[kQKV*kE];
__device__ __half g_qh[kBH*kS*kD], g_ql[kBH*kS*kD];
__device__ __half g_kh[kBH*kS*kD], g_kl[kBH*kS*kD];
__device__ __half g_vth[kBH*kD*kS], g_vtl[kBH*kD*kS];
__device__ __half g_ph[(size_t)kBH*kS*kS], g_pl[(size_t)kBH*kS*kS];
__device__ __half g_o2h[kBS*kE], g_o2l[kBS*kE];
__device__ __half g_wph[kE*kE],  g_wpl[kE*kE];
__device__ __half g_wuh[kF*kE],  g_wul[kF*kE];
__device__ __half g_wgh[kF*kE],  g_wgl[kF*kE];
__device__ __half g_wdh[kE*kF],  g_wdl[kE*kF];
__device__ __half g_hh[kBS*kE],  g_hl[kBS*kE];
__device__ __half g_uh[kBS*kF],  g_ul[kBS*kF];
__device__ __half g_pwh[(size_t)kV*kE], g_pwl[(size_t)kV*kE];

// ------------------------- PTX helpers -------------------------
__device__ __forceinline__ uint32_t smem_u32(const void* p) {
    uint32_t a;
    asm("{ .reg .u64 t; cvta.to.shared.u64 t, %1; cvt.u32.u64 %0, t; }" : "=r"(a) : "l"(p));
    return a;
}
__device__ __forceinline__ void cpasync16(uint32_t dst, const void* src) {
    asm volatile("cp.async.cg.shared.global [%0], [%1], 16;" :: "r"(dst), "l"(src));
}
#define CP_COMMIT() asm volatile("cp.async.commit_group;" ::: "memory")
#define CP_WAIT1()  asm volatile("cp.async.wait_group 1;" ::: "memory")
#define CP_WAIT0()  asm volatile("cp.async.wait_group 0;" ::: "memory")

__device__ __forceinline__ void ldsm4(uint32_t* r, uint32_t addr) {
    asm volatile("ldmatrix.sync.aligned.m8n8.x4.shared.b16 {%0,%1,%2,%3}, [%4];"
        : "=r"(r[0]), "=r"(r[1]), "=r"(r[2]), "=r"(r[3]) : "r"(addr));
}
__device__ __forceinline__ void hmma(float* c, const uint32_t* a, const uint32_t* b) {
    asm volatile("mma.sync.aligned.m16n8k16.row.col.f32.f16.f16.f32 "
        "{%0,%1,%2,%3}, {%4,%5,%6,%7}, {%8,%9}, {%0,%1,%2,%3};"
        : "+f"(c[0]), "+f"(c[1]), "+f"(c[2]), "+f"(c[3])
        : "r"(a[0]), "r"(a[1]), "r"(a[2]), "r"(a[3]), "r"(b[0]), "r"(b[1]));
}
__device__ __forceinline__ void split2(float v, __half* h, __half* l) {
    __half hi = __float2half(v);
    *h = hi;
    *l = __float2half((v - __half2float(hi)) * 1024.f);
}

// stage one ROWS x 64 fp16 tile into 144B-padded smem rows via cp.async
template<int ROWS>
__device__ __forceinline__ void stage_cp(uint32_t dst, const __half* __restrict__ src,
                                         long long ld, int k0, int tid)
{
#pragma unroll
    for (int it = 0; it < ROWS * 8 / 256; it++) {
        int i = it * 256 + tid;
        int r = i >> 3, c = i & 7;
        cpasync16(dst + r * 144 + c * 16, src + (long long)r * ld + k0 + c * 8);
    }
}

// ------------------------- HMMA GEMM -------------------------
// C[M,N] = alpha * (A @ B^T) (+bias[n]) (+C). A:[M,K] hi/lo fp16 K-major,
// B:[N,K] hi/lo fp16 K-major. BM=128, BK=64, 2-stage cp.async pipeline.
// lo is pre-scaled by 1024. CAUSAL: skip tiles above diagonal.
// CAUSK: clamp K at (by+1)*128.
template<int BN, bool ACCUM, bool BIAS, bool CAUSAL, bool CAUSK>
__global__ void __launch_bounds__(256, 1)
tgemm_k(const __half* __restrict__ Ah, const __half* __restrict__ Al, int lda, long long sA,
        const __half* __restrict__ Bh, const __half* __restrict__ Bl, int ldb, long long sB,
        float* __restrict__ C, int ldc, long long sC,
        const float* __restrict__ bias, float alpha, int K)
{
    constexpr int BM = 128, BK = 64;
    constexpr int WM = (BN == 128) ? 2 : 4;     // warp grid (M x N), 8 warps
    constexpr int WN = 8 / WM;
    constexpr int MT = BM / (WM * 16);
    constexpr int NT = BN / (WN * 8);
    constexpr int TILEA = BM * 144;
    constexpr int TILEB = BN * 144;
    constexpr int STAGE = 2 * TILEA + 2 * TILEB;

    const int bx = blockIdx.x, by = blockIdx.y, bz = blockIdx.z;
    if (CAUSAL && bx * BN > by * BM + BM - 1) return;
    int Ktot = K;
    if (CAUSK) { int km = (by + 1) * BM; if (km < Ktot) Ktot = km; }
    const int NC = Ktot / BK;

    extern __shared__ char sm[];
    const uint32_t sb = smem_u32(sm);
    const int tid = threadIdx.x, lane = tid & 31, wid = tid >> 5;
    const int m0 = (wid / WN) * MT * 16;
    const int n0 = (wid % WN) * NT * 8;

    const __half* pAh = Ah + bz * sA + (long long)by * BM * lda;
    const __half* pAl = Al + bz * sA + (long long)by * BM * lda;
    const __half* pBh = Bh + bz * sB + (long long)bx * BN * ldb;
    const __half* pBl = Bl + bz * sB + (long long)bx * BN * ldb;

    float acc1[MT][NT][4];
    float acc2[MT][NT][4];
#pragma unroll
    for (int mt = 0; mt < MT; mt++)
#pragma unroll
        for (int nt = 0; nt < NT; nt++)
#pragma unroll
            for (int i = 0; i < 4; i++) { acc1[mt][nt][i] = 0.f; acc2[mt][nt][i] = 0.f; }

    auto stage_all = [&](int buf, int k0) {
        uint32_t s0 = sb + (uint32_t)buf * STAGE;
        stage_cp<BM>(s0,                    pAh, lda, k0, tid);
        stage_cp<BM>(s0 + TILEA,            pAl, lda, k0, tid);
        stage_cp<BN>(s0 + 2*TILEA,          pBh, ldb, k0, tid);
        stage_cp<BN>(s0 + 2*TILEA + TILEB,  pBl, ldb, k0, tid);
    };

    stage_all(0, 0); CP_COMMIT();

    for (int i = 0; i < NC; i++) {
        if (i + 1 < NC) { stage_all((i + 1) & 1, (i + 1) * BK); CP_COMMIT(); CP_WAIT1(); }
        else            { CP_WAIT0(); }
        __syncthreads();

        const uint32_t s0 = sb + (uint32_t)(i & 1) * STAGE;
        const uint32_t aH = s0, aL = s0 + TILEA;
        const uint32_t bH = s0 + 2*TILEA, bL = s0 + 2*TILEA + TILEB;

#pragma unroll
        for (int ks = 0; ks < 4; ks++) {
            const int kc = ks * 2;
            uint32_t ah[MT][4], al[MT][4], bhf[NT][2], blf[NT][2];

#pragma unroll
            for (int nt = 0; nt < NT; nt += 2) {
                const int g = lane >> 3;
                const uint32_t off =
                    (uint32_t)(n0 + nt * 8 + ((g >> 1) << 3) + (lane & 7)) * 144
                    + (uint32_t)(kc + (g & 1)) * 16;
                uint32_t r[4];
                ldsm4(r, bH + off);
                bhf[nt][0] = r[0]; bhf[nt][1] = r[1];
                bhf[nt+1][0] = r[2]; bhf[nt+1][1] = r[3];
                ldsm4(r, bL + off);
                blf[nt][0] = r[0]; blf[nt][1] = r[1];
                blf[nt+1][0] = r[2]; blf[nt+1][1] = r[3];
            }
#pragma unroll
            for (int mt = 0; mt < MT; mt++) {
                const uint32_t off =
                    (uint32_t)(m0 + mt * 16 + (lane & 15)) * 144
                    + (uint32_t)(kc + (lane >> 4)) * 16;
                ldsm4(ah[mt], aH + off);
                ldsm4(al[mt], aL + off);
            }
#pragma unroll
            for (int mt = 0; mt < MT; mt++)
#pragma unroll
                for (int nt = 0; nt < NT; nt++) {
                    hmma(acc1[mt][nt], ah[mt], bhf[nt]);
                    hmma(acc2[mt][nt], ah[mt], blf[nt]);
                    hmma(acc2[mt][nt], al[mt], bhf[nt]);
                }
        }
        __syncthreads();
    }

    // ---- epilogue: direct register -> global ----
    const float inv = 1.f / 1024.f;
    float* Cp = C + bz * sC;
#pragma unroll
    for (int mt = 0; mt < MT; mt++) {
#pragma unroll
        for (int nt = 0; nt < NT; nt++) {
            const int row = by * BM + m0 + mt * 16 + (lane >> 2);
            const int col = bx * BN + n0 + nt * 8 + ((lane & 3) << 1);
#pragma unroll
            for (int h = 0; h < 2; h++) {
                const int r = row + h * 8;
                float v0 = (acc1[mt][nt][2*h]   + acc2[mt][nt][2*h]   * inv) * alpha;
                float v1 = (acc1[mt][nt][2*h+1] + acc2[mt][nt][2*h+1] * inv) * alpha;
                if (BIAS) { v0 += bias[col]; v1 += bias[col + 1]; }
                float2* p = reinterpret_cast<float2*>(Cp + (long long)r * ldc + col);
                if (ACCUM) { float2 o = *p; v0 += o.x; v1 += o.y; }
                *p = make_float2(v0, v1);
            }
        }
    }
}

// ------------------------- elementwise kernels -------------------------
__global__ void embed_k(const int* __restrict__ tok, const float* __restrict__ tab,
                        float* __restrict__ out, __half* __restrict__ eh, __half* __restrict__ el)
{
    int idx = blockIdx.x * blockDim.x + threadIdx.x;
    float v = tab[(size_t)tok[idx >> 10] * kE + (idx & 1023)];
    out[idx] = v; split2(v, eh + idx, el + idx);
}

__global__ void costab_k(float* __restrict__ ct, float* __restrict__ st)
{
    int idx = blockIdx.x * blockDim.x + threadIdx.x;
    int s = idx / kD, i = idx % kD;
    float theta = powf(10000.f, (-2.f / kD) * (float)(i & 31));
    ct[idx] = cosf((float)s * theta);
    st[idx] = sinf((float)s * theta) * (i < kD/2 ? -1.f : 1.f);
}

__global__ void wqkv_k(const float* __restrict__ wq, const float* __restrict__ wk,
                       const float* __restrict__ wv, __half* __restrict__ h, __half* __restrict__ l)
{
    int idx = blockIdx.x * blockDim.x + threadIdx.x;   // kQKV*kE
    int n = idx / kE, e = idx % kE;
    int seg = n >> 10, hh = (n & 1023) >> 6, k = n & 63;
    const float* w = seg == 0 ? wq : seg == 1 ? wk : wv;
    split2(w[((size_t)hh * kE + e) * kD + k], h + idx, l + idx);
}

__global__ void wtr_k(const float* __restrict__ src, __half* __restrict__ dh,
                      __half* __restrict__ dl, int K, int N)
{
    __shared__ float t[32][33];
    int k0 = blockIdx.y * 32, n0 = blockIdx.x * 32;
    for (int r = threadIdx.y; r < 32; r += 8)
        t[r][threadIdx.x] = src[(size_t)(k0 + r) * N + n0 + threadIdx.x];
    __syncthreads();
    for (int r = threadIdx.y; r < 32; r += 8) {
        size_t o = (size_t)(n0 + r) * K + k0 + threadIdx.x;
        split2(t[threadIdx.x][r], dh + o, dl + o);
    }
}

__global__ void rope_k(const float* __restrict__ qkv, const float* __restrict__ ct,
                       const float* __restrict__ st,
                       __half* __restrict__ qh, __half* __restrict__ ql,
                       __half* __restrict__ kh, __half* __restrict__ kl,
                       __half* __restrict__ vth, __half* __restrict__ vtl)
{
    int idx = blockIdx.x * blockDim.x + threadIdx.x;   // kBS*kQKV
    int row = idx / kQKV, c = idx % kQKV;
    int b = row >> 10, s = row & 1023;
    int seg = c >> 10, h = (c & 1023) >> 6, i = c & 63;
    float x = qkv[idx];
    if (seg == 2) {
        size_t dst = ((size_t)(b * kH + h) * kD + i) * kS + s;
        split2(x, vth + dst, vtl + dst);
        return;
    }
    float sw = qkv[(size_t)row * kQKV + (seg << 10) + (h << 6) + ((i + 32) & 63)];
    float val = ct[(s << 6) + i] * x + st[(s << 6) + i] * sw;
    size_t dst = ((size_t)(b * kH + h) * kS + s) * kD + i;
    if (seg == 0) split2(val, qh + dst, ql + dst);
    else          split2(val, kh + dst, kl + dst);
}

// register-resident causal softmax: 256 threads, 4 cols/thread; no fp32 writeback
__global__ void softmax_k(const float* __restrict__ sc,
                          __half* __restrict__ ph, __half* __restrict__ pl)
{
    const int r = blockIdx.x, s = r & (kS - 1), n = s + 1, t = threadIdx.x;
    const float* row = sc + (size_t)r * kS;
    __half* prh = ph + (size_t)r * kS;
    __half* prl = pl + (size_t)r * kS;
    __shared__ float red[256];

    float v[4];
#pragma unroll
    for (int j = 0; j < 4; j++) {
        int i = t + j * 256;
        v[j] = (i < n) ? row[i] : -INFINITY;
    }
    float m = fmaxf(fmaxf(v[0], v[1]), fmaxf(v[2], v[3]));
    red[t] = m; __syncthreads();
    for (int o = 128; o > 0; o >>= 1) { if (t < o) red[t] = fmaxf(red[t], red[t+o]); __syncthreads(); }
    m = red[0]; __syncthreads();

    float e[4], sum = 0.f;
#pragma unroll
    for (int j = 0; j < 4; j++) {
        int i = t + j * 256;
        e[j] = (i < n) ? expf(v[j] - m) : 0.f;
        sum += e[j];
    }
    red[t] = sum; __syncthreads();
    for (int o = 128; o > 0; o >>= 1) { if (t < o) red[t] += red[t+o]; __syncthreads(); }
    float inv = 1.f / red[0];
#pragma unroll
    for (int j = 0; j < 4; j++) {
        int i = t + j * 256;
        split2(e[j] * inv, prh + i, prl + i);
    }
}

__global__ void oresh_k(const float* __restrict__ o, __half* __restrict__ oh, __half* __restrict__ ol)
{
    int idx = blockIdx.x * blockDim.x + threadIdx.x;   // kBH*kS*kD
    int bh = idx / (kS * kD), rem = idx % (kS * kD);
    int s = rem >> 6, d = rem & 63, b = bh / kH, h = bh % kH;
    size_t dst = ((size_t)(b * kS + s) << 10) + (h << 6) + d;
    split2(o[idx], oh + dst, ol + dst);
}

__global__ void split_k(const float* __restrict__ x, __half* __restrict__ h, __half* __restrict__ l)
{
    int i = blockIdx.x * blockDim.x + threadIdx.x;
    split2(x[i], h + i, l + i);
}

__global__ void rmsnorm_k(const float* __restrict__ x, const float* __restrict__ w,
                          __half* __restrict__ yh, __half* __restrict__ yl)
{
    const int r = blockIdx.x, t = threadIdx.x;
    const float* xr = x + (size_t)r * kE;
    __shared__ float red[256];
    float sum = 0.f;
    for (int i = t; i < kE; i += 256) { float v = xr[i]; sum += v * v; }
    red[t] = sum; __syncthreads();
    for (int o = 128; o > 0; o >>= 1) { if (t < o) red[t] += red[t+o]; __syncthreads(); }
    float rs = rsqrtf(red[0] / kE + 1.1920929e-7f);
    for (int i = t; i < kE; i += 256) {
        size_t o = (size_t)r * kE + i;
        split2(xr[i] * rs * w[i], yh + o, yl + o);
    }
}

__global__ void elumul_k(const float* __restrict__ u, const float* __restrict__ g,
                         __half* __restrict__ uh, __half* __restrict__ ul)
{
    int i = blockIdx.x * blockDim.x + threadIdx.x;
    float gv = g[i];
    split2(u[i] * (gv > 0.f ? gv : expm1f(gv)), uh + i, ul + i);
}

// ------------------------- host launcher -------------------------
#define SYM(p, s) cudaGetSymbolAddress((void**)&p, s)

extern "C" void kernel_launch(void* const* d_in, const int* in_sizes, int n_in,
                              void* d_out, int out_size)
{
    (void)in_sizes; (void)n_in; (void)out_size;
    const int*   tokens = (const int*)  d_in[0];
    const float* table = (const float*)d_in[1];
    const float *Wq = (const float*)d_in[2], *Wk = (const float*)d_in[3], *Wv = (const float*)d_in[4];
    const float *Wproj = (const float*)d_in[5], *normw = (const float*)d_in[6];
    const float *Wup = (const float*)d_in[7], *Wgate = (const float*)d_in[8], *Wdown = (const float*)d_in[9];
    const float *predW = (const float*)d_in[10], *predB = (const float*)d_in[11];
    float* logits = (float*)d_out;

    float *emb, *qkv, *sc, *o, *u, *g, *ct, *st;
    __half *eh, *el, *wqkvh, *wqkvl, *qh, *ql, *kh, *kl, *vth, *vtl, *ph, *pl;
    __half *o2h, *o2l, *wph, *wpl, *wuh, *wul, *wgh, *wgl, *wdh, *wdl, *hh, *hl, *uh, *ul, *pwh, *pwl;
    SYM(emb, g_emb); SYM(qkv, g_qkv); SYM(sc, g_sc); SYM(o, g_o); SYM(u, g_u); SYM(g, g_g);
    SYM(ct, g_ct); SYM(st, g_st);
    SYM(eh, g_eh); SYM(el, g_el); SYM(wqkvh, g_wqkvh); SYM(wqkvl, g_wqkvl);
    SYM(qh, g_qh); SYM(ql, g_ql); SYM(kh, g_kh); SYM(kl, g_kl);
    SYM(vth, g_vth); SYM(vtl, g_vtl); SYM(ph, g_ph); SYM(pl, g_pl);
    SYM(o2h, g_o2h); SYM(o2l, g_o2l); SYM(wph, g_wph); SYM(wpl, g_wpl);
    SYM(wuh, g_wuh); SYM(wul, g_wul); SYM(wgh, g_wgh); SYM(wgl, g_wgl);
    SYM(wdh, g_wdh); SYM(wdl, g_wdl); SYM(hh, g_hh); SYM(hl, g_hl);
    SYM(uh, g_uh); SYM(ul, g_ul); SYM(pwh, g_pwh); SYM(pwl, g_pwl);

    const int SM128 = 2 * (2 * 128 * 144 + 2 * 128 * 144);  // 147456
    const int SM64  = 2 * (2 * 128 * 144 + 2 * 64 * 144);   // 110592
    cudaFuncSetAttribute(tgemm_k<128,false,false,false,false>, cudaFuncAttributeMaxDynamicSharedMemorySize, SM128);
    cudaFuncSetAttribute(tgemm_k<128,false,false,true ,false>, cudaFuncAttributeMaxDynamicSharedMemorySize, SM128);
    cudaFuncSetAttribute(tgemm_k<128,true ,false,false,false>, cudaFuncAttributeMaxDynamicSharedMemorySize, SM128);
    cudaFuncSetAttribute(tgemm_k<128,false,true ,false,false>, cudaFuncAttributeMaxDynamicSharedMemorySize, SM128);
    cudaFuncSetAttribute(tgemm_k<64 ,false,false,false,true >, cudaFuncAttributeMaxDynamicSharedMemorySize, SM64);

    embed_k <<<kBS * kE / 256, 256>>>(tokens, table, emb, eh, el);
    costab_k<<<kS * kD / 256, 256>>>(ct, st);

    for (int l = 0; l < 4; l++) {
        const float* wq = Wq    + (size_t)l * kH * kE * kD;
        const float* wk = Wk    + (size_t)l * kH * kE * kD;
        const float* wv = Wv    + (size_t)l * kH * kE * kD;
        const float* wp = Wproj + (size_t)l * kE * kE;
        const float* nw = normw + (size_t)l * kE;
        const float* wu = Wup   + (size_t)l * kE * kF;
        const float* wg = Wgate + (size_t)l * kE * kF;
        const float* wd = Wdown + (size_t)l * kF * kE;

        // QKV: [2048,1024] x [3072,1024]^T
        wqkv_k<<<kQKV * kE / 256, 256>>>(wq, wk, wv, wqkvh, wqkvl);
        tgemm_k<128,false,false,false,false><<<dim3(kQKV/128, kBS/128), 256, SM128>>>(
            eh, el, kE, 0, wqkvh, wqkvl, kE, 0, qkv, kQKV, 0, nullptr, 1.f, kE);
        rope_k<<<kBS * kQKV / 256, 256>>>(qkv, ct, st, qh, ql, kh, kl, vth, vtl);

        // scores = q @ k^T / 8 (causal tile-skip)
        tgemm_k<128,false,false,true,false><<<dim3(kS/128, kS/128, kBH), 256, SM128>>>(
            qh, ql, kD, (long long)kS*kD, kh, kl, kD, (long long)kS*kD,
            sc, kS, (long long)kS*kS, nullptr, 0.125f, kD);
        softmax_k<<<kBH * kS, 256>>>(sc, ph, pl);

        // o = P @ V (causal K-bound)
        tgemm_k<64,false,false,false,true><<<dim3(1, kS/128, kBH), 256, SM64>>>(
            ph, pl, kS, (long long)kS*kS, vth, vtl, kS, (long long)kD*kS,
            o, kD, (long long)kS*kD, nullptr, 1.f, kS);
        oresh_k<<<kBH * kS * kD / 256, 256>>>(o, o2h, o2l);

        // emb += o2 @ Wproj
        wtr_k<<<dim3(kE/32, kE/32), dim3(32,8)>>>(wp, wph, wpl, kE, kE);
        tgemm_k<128,true,false,false,false><<<dim3(kE/128, kBS/128), 256, SM128>>>(
            o2h, o2l, kE, 0, wph, wpl, kE, 0, emb, kE, 0, nullptr, 1.f, kE);

        // MLP
        rmsnorm_k<<<kBS, 256>>>(emb, nw, hh, hl);
        wtr_k<<<dim3(kF/32, kE/32), dim3(32,8)>>>(wu, wuh, wul, kE, kF);
        wtr_k<<<dim3(kF/32, kE/32), dim3(32,8)>>>(wg, wgh, wgl, kE, kF);
        tgemm_k<128,false,false,false,false><<<dim3(kF/128, kBS/128), 256, SM128>>>(
            hh, hl, kE, 0, wuh, wul, kE, 0, u, kF, 0, nullptr, 1.f, kE);
        tgemm_k<128,false,false,false,false><<<dim3(kF/128, kBS/128), 256, SM128>>>(
            hh, hl, kE, 0, wgh, wgl, kE, 0, g, kF, 0, nullptr, 1.f, kE);
        elumul_k<<<kBS * kF / 256, 256>>>(u, g, uh, ul);
        wtr_k<<<dim3(kE/32, kF/32), dim3(32,8)>>>(wd, wdh, wdl, kF, kE);
        tgemm_k<128,true,false,false,false><<<dim3(kE/128, kBS/128), 256, SM128>>>(
            uh, ul, kF, 0, wdh, wdl, kF, 0, emb, kE, 0, nullptr, 1.f, kF);
        split_k<<<kBS * kE / 256, 256>>>(emb, eh, el);
    }

    // logits = emb @ predW + predB : [2048,1024] x [32000,1024]^T
    wtr_k<<<dim3(kV/32, kE/32), dim3(32,8)>>>(predW, pwh, pwl, kE, kV);
    tgemm_k<128,false,true,false,false><<<dim3(kV/128, kBS/128), 256, SM128>>>(
        eh, el, kE, 0, pwh, pwl, kE, 0, logits, kV, 0, predB, 1.f, kE);
}

// round 6
// speedup vs baseline: 2.3849x; 1.0015x over previous
#include <cuda_runtime.h>
#include <cuda_fp16.h>
#include <math.h>
#include <stdint.h>

namespace {
constexpr int kB = 2, kS = 1024, kE = 1024, kH = 16, kD = 64, kF = 4096, kV = 32000;
constexpr int kBS = kB * kS, kBH = kB * kH, kQKV = 3 * kE;
}

// ------------------------- device scratch -------------------------
__device__ float  g_emb [kBS * kE];
__device__ float  g_qkv [kBS * kQKV];
__device__ float  g_sc  [(size_t)kBH * kS * kS];
__device__ float  g_o   [kBH * kS * kD];
__device__ float  g_u   [kBS * kF];
__device__ float  g_g   [kBS * kF];
__device__ float  g_ct  [kS * kD];
__device__ float  g_st  [kS * kD];

__device__ __half g_eh[kBS*kE], g_el[kBS*kE];
__device__ __half g_wqkvh[kQKV*kE], g_wqkvl[kQKV*kE];
__device__ __half g_qh[kBH*kS*kD], g_ql[kBH*kS*kD];
__device__ __half g_kh[kBH*kS*kD], g_kl[kBH*kS*kD];
__device__ __half g_vth[kBH*kD*kS], g_vtl[kBH*kD*kS];
__device__ __half g_ph[(size_t)kBH*kS*kS], g_pl[(size_t)kBH*kS*kS];
__device__ __half g_o2h[kBS*kE], g_o2l[kBS*kE];
__device__ __half g_wph[kE*kE],  g_wpl[kE*kE];
__device__ __half g_wuh[kF*kE],  g_wul[kF*kE];
__device__ __half g_wgh[kF*kE],  g_wgl[kF*kE];
__device__ __half g_wdh[kE*kF],  g_wdl[kE*kF];
__device__ __half g_hh[kBS*kE],  g_hl[kBS*kE];
__device__ __half g_uh[kBS*kF],  g_ul[kBS*kF];
__device__ __half g_pwh[(size_t)kV*kE], g_pwl[(size_t)kV*kE];

// ------------------------- PTX helpers -------------------------
__device__ __forceinline__ uint32_t smem_u32(const void* p) {
    uint32_t a;
    asm("{ .reg .u64 t; cvta.to.shared.u64 t, %1; cvt.u32.u64 %0, t; }" : "=r"(a) : "l"(p));
    return a;
}
__device__ __forceinline__ void cpasync16(uint32_t dst, const void* src) {
    asm volatile("cp.async.cg.shared.global [%0], [%1], 16;" :: "r"(dst), "l"(src));
}
#define CP_COMMIT() asm volatile("cp.async.commit_group;" ::: "memory")
#define CP_WAIT0()  asm volatile("cp.async.wait_group 0;" ::: "memory")

__device__ __forceinline__ void ldsm4(uint32_t* r, uint32_t addr) {
    asm volatile("ldmatrix.sync.aligned.m8n8.x4.shared.b16 {%0,%1,%2,%3}, [%4];"
        : "=r"(r[0]), "=r"(r[1]), "=r"(r[2]), "=r"(r[3]) : "r"(addr));
}
__device__ __forceinline__ void hmma(float* c, const uint32_t* a, const uint32_t* b) {
    asm volatile("mma.sync.aligned.m16n8k16.row.col.f32.f16.f16.f32 "
        "{%0,%1,%2,%3}, {%4,%5,%6,%7}, {%8,%9}, {%0,%1,%2,%3};"
        : "+f"(c[0]), "+f"(c[1]), "+f"(c[2]), "+f"(c[3])
        : "r"(a[0]), "r"(a[1]), "r"(a[2]), "r"(a[3]), "r"(b[0]), "r"(b[1]));
}
__device__ __forceinline__ void split2(float v, __half* h, __half* l) {
    __half hi = __float2half(v);
    *h = hi;
    *l = __float2half((v - __half2float(hi)) * 1024.f);
}

// stage one ROWS x 64 fp16 tile into 144B-padded smem rows via cp.async
template<int ROWS>
__device__ __forceinline__ void stage_cp(uint32_t dst, const __half* __restrict__ src,
                                         long long ld, int k0, int tid)
{
#pragma unroll
    for (int it = 0; it < ROWS * 8 / 256; it++) {
        int i = it * 256 + tid;
        int r = i >> 3, c = i & 7;
        cpasync16(dst + r * 144 + c * 16, src + (long long)r * ld + k0 + c * 8);
    }
}

// ------------------------- HMMA GEMM -------------------------
// C[M,N] = alpha * (A @ B^T) (+bias[n]) (+C). A:[M,K] hi/lo fp16 K-major,
// B:[N,K] hi/lo fp16 K-major. BM=128, BK=64, 2-stage cp.async pipeline,
// ONE __syncthreads per K-chunk (stage is issued after the barrier, so the
// barrier proves all warps finished reading the buffer being overwritten).
// lo is pre-scaled by 1024. CAUSAL: skip tiles above diagonal.
// CAUSK: clamp K at (by+1)*128.
template<int BN, bool ACCUM, bool BIAS, bool CAUSAL, bool CAUSK>
__global__ void __launch_bounds__(256, 1)
tgemm_k(const __half* __restrict__ Ah, const __half* __restrict__ Al, int lda, long long sA,
        const __half* __restrict__ Bh, const __half* __restrict__ Bl, int ldb, long long sB,
        float* __restrict__ C, int ldc, long long sC,
        const float* __restrict__ bias, float alpha, int K)
{
    constexpr int BM = 128, BK = 64;
    constexpr int WM = (BN == 128) ? 2 : 4;     // warp grid (M x N), 8 warps
    constexpr int WN = 8 / WM;
    constexpr int MT = BM / (WM * 16);
    constexpr int NT = BN / (WN * 8);
    constexpr int TILEA = BM * 144;
    constexpr int TILEB = BN * 144;
    constexpr int STAGE = 2 * TILEA + 2 * TILEB;

    const int bx = blockIdx.x, by = blockIdx.y, bz = blockIdx.z;
    if (CAUSAL && bx * BN > by * BM + BM - 1) return;
    int Ktot = K;
    if (CAUSK) { int km = (by + 1) * BM; if (km < Ktot) Ktot = km; }
    const int NC = Ktot / BK;

    extern __shared__ char sm[];
    const uint32_t sb = smem_u32(sm);
    const int tid = threadIdx.x, lane = tid & 31, wid = tid >> 5;
    const int m0 = (wid / WN) * MT * 16;
    const int n0 = (wid % WN) * NT * 8;

    const __half* pAh = Ah + bz * sA + (long long)by * BM * lda;
    const __half* pAl = Al + bz * sA + (long long)by * BM * lda;
    const __half* pBh = Bh + bz * sB + (long long)bx * BN * ldb;
    const __half* pBl = Bl + bz * sB + (long long)bx * BN * ldb;

    float acc1[MT][NT][4];
    float acc2[MT][NT][4];
#pragma unroll
    for (int mt = 0; mt < MT; mt++)
#pragma unroll
        for (int nt = 0; nt < NT; nt++)
#pragma unroll
            for (int i = 0; i < 4; i++) { acc1[mt][nt][i] = 0.f; acc2[mt][nt][i] = 0.f; }

    auto stage_all = [&](int buf, int k0) {
        uint32_t s0 = sb + (uint32_t)buf * STAGE;
        stage_cp<BM>(s0,                    pAh, lda, k0, tid);
        stage_cp<BM>(s0 + TILEA,            pAl, lda, k0, tid);
        stage_cp<BN>(s0 + 2*TILEA,          pBh, ldb, k0, tid);
        stage_cp<BN>(s0 + 2*TILEA + TILEB,  pBl, ldb, k0, tid);
    };

    stage_all(0, 0); CP_COMMIT();

    for (int i = 0; i < NC; i++) {
        CP_WAIT0();               // chunk i landed (only group in flight)
        __syncthreads();          // all warps done with chunk i-1 => buffer (i+1)&1 free
        if (i + 1 < NC) { stage_all((i + 1) & 1, (i + 1) * BK); CP_COMMIT(); }

        const uint32_t s0 = sb + (uint32_t)(i & 1) * STAGE;
        const uint32_t aH = s0, aL = s0 + TILEA;
        const uint32_t bH = s0 + 2*TILEA, bL = s0 + 2*TILEA + TILEB;

#pragma unroll
        for (int ks = 0; ks < 4; ks++) {
            const int kc = ks * 2;
            uint32_t ah[MT][4], al[MT][4], bhf[NT][2], blf[NT][2];

#pragma unroll
            for (int nt = 0; nt < NT; nt += 2) {
                const int g = lane >> 3;
                const uint32_t off =
                    (uint32_t)(n0 + nt * 8 + ((g >> 1) << 3) + (lane & 7)) * 144
                    + (uint32_t)(kc + (g & 1)) * 16;
                uint32_t r[4];
                ldsm4(r, bH + off);
                bhf[nt][0] = r[0]; bhf[nt][1] = r[1];
                bhf[nt+1][0] = r[2]; bhf[nt+1][1] = r[3];
                ldsm4(r, bL + off);
                blf[nt][0] = r[0]; blf[nt][1] = r[1];
                blf[nt+1][0] = r[2]; blf[nt+1][1] = r[3];
            }
#pragma unroll
            for (int mt = 0; mt < MT; mt++) {
                const uint32_t off =
                    (uint32_t)(m0 + mt * 16 + (lane & 15)) * 144
                    + (uint32_t)(kc + (lane >> 4)) * 16;
                ldsm4(ah[mt], aH + off);
                ldsm4(al[mt], aL + off);
            }
#pragma unroll
            for (int mt = 0; mt < MT; mt++)
#pragma unroll
                for (int nt = 0; nt < NT; nt++) {
                    hmma(acc1[mt][nt], ah[mt], bhf[nt]);
                    hmma(acc2[mt][nt], ah[mt], blf[nt]);
                    hmma(acc2[mt][nt], al[mt], bhf[nt]);
                }
        }
    }

    // ---- epilogue: direct register -> global ----
    const float inv = 1.f / 1024.f;
    float* Cp = C + bz * sC;
#pragma unroll
    for (int mt = 0; mt < MT; mt++) {
#pragma unroll
        for (int nt = 0; nt < NT; nt++) {
            const int row = by * BM + m0 + mt * 16 + (lane >> 2);
            const int col = bx * BN + n0 + nt * 8 + ((lane & 3) << 1);
#pragma unroll
            for (int h = 0; h < 2; h++) {
                const int r = row + h * 8;
                float v0 = (acc1[mt][nt][2*h]   + acc2[mt][nt][2*h]   * inv) * alpha;
                float v1 = (acc1[mt][nt][2*h+1] + acc2[mt][nt][2*h+1] * inv) * alpha;
                if (BIAS) { v0 += bias[col]; v1 += bias[col + 1]; }
                float2* p = reinterpret_cast<float2*>(Cp + (long long)r * ldc + col);
                if (ACCUM) { float2 o = *p; v0 += o.x; v1 += o.y; }
                *p = make_float2(v0, v1);
            }
        }
    }
}

// ------------------------- elementwise kernels -------------------------
__global__ void embed_k(const int* __restrict__ tok, const float* __restrict__ tab,
                        float* __restrict__ out, __half* __restrict__ eh, __half* __restrict__ el)
{
    int idx = blockIdx.x * blockDim.x + threadIdx.x;
    float v = tab[(size_t)tok[idx >> 10] * kE + (idx & 1023)];
    out[idx] = v; split2(v, eh + idx, el + idx);
}

__global__ void costab_k(float* __restrict__ ct, float* __restrict__ st)
{
    int idx = blockIdx.x * blockDim.x + threadIdx.x;
    int s = idx / kD, i = idx % kD;
    float theta = powf(10000.f, (-2.f / kD) * (float)(i & 31));
    ct[idx] = cosf((float)s * theta);
    st[idx] = sinf((float)s * theta) * (i < kD/2 ? -1.f : 1.f);
}

__global__ void wqkv_k(const float* __restrict__ wq, const float* __restrict__ wk,
                       const float* __restrict__ wv, __half* __restrict__ h, __half* __restrict__ l)
{
    int idx = blockIdx.x * blockDim.x + threadIdx.x;   // kQKV*kE
    int n = idx / kE, e = idx % kE;
    int seg = n >> 10, hh = (n & 1023) >> 6, k = n & 63;
    const float* w = seg == 0 ? wq : seg == 1 ? wk : wv;
    split2(w[((size_t)hh * kE + e) * kD + k], h + idx, l + idx);
}

__global__ void wtr_k(const float* __restrict__ src, __half* __restrict__ dh,
                      __half* __restrict__ dl, int K, int N)
{
    __shared__ float t[32][33];
    int k0 = blockIdx.y * 32, n0 = blockIdx.x * 32;
    for (int r = threadIdx.y; r < 32; r += 8)
        t[r][threadIdx.x] = src[(size_t)(k0 + r) * N + n0 + threadIdx.x];
    __syncthreads();
    for (int r = threadIdx.y; r < 32; r += 8) {
        size_t o = (size_t)(n0 + r) * K + k0 + threadIdx.x;
        split2(t[threadIdx.x][r], dh + o, dl + o);
    }
}

__global__ void rope_k(const float* __restrict__ qkv, const float* __restrict__ ct,
                       const float* __restrict__ st,
                       __half* __restrict__ qh, __half* __restrict__ ql,
                       __half* __restrict__ kh, __half* __restrict__ kl,
                       __half* __restrict__ vth, __half* __restrict__ vtl)
{
    int idx = blockIdx.x * blockDim.x + threadIdx.x;   // kBS*kQKV
    int row = idx / kQKV, c = idx % kQKV;
    int b = row >> 10, s = row & 1023;
    int seg = c >> 10, h = (c & 1023) >> 6, i = c & 63;
    float x = qkv[idx];
    if (seg == 2) {
        size_t dst = ((size_t)(b * kH + h) * kD + i) * kS + s;
        split2(x, vth + dst, vtl + dst);
        return;
    }
    float sw = qkv[(size_t)row * kQKV + (seg << 10) + (h << 6) + ((i + 32) & 63)];
    float val = ct[(s << 6) + i] * x + st[(s << 6) + i] * sw;
    size_t dst = ((size_t)(b * kH + h) * kS + s) * kD + i;
    if (seg == 0) split2(val, qh + dst, ql + dst);
    else          split2(val, kh + dst, kl + dst);
}

// register-resident causal softmax: 256 threads, 4 cols/thread
__global__ void softmax_k(const float* __restrict__ sc,
                          __half* __restrict__ ph, __half* __restrict__ pl)
{
    const int r = blockIdx.x, s = r & (kS - 1), n = s + 1, t = threadIdx.x;
    const float* row = sc + (size_t)r * kS;
    __half* prh = ph + (size_t)r * kS;
    __half* prl = pl + (size_t)r * kS;
    __shared__ float red[256];

    float v[4];
#pragma unroll
    for (int j = 0; j < 4; j++) {
        int i = t + j * 256;
        v[j] = (i < n) ? row[i] : -INFINITY;
    }
    float m = fmaxf(fmaxf(v[0], v[1]), fmaxf(v[2], v[3]));
    red[t] = m; __syncthreads();
    for (int o = 128; o > 0; o >>= 1) { if (t < o) red[t] = fmaxf(red[t], red[t+o]); __syncthreads(); }
    m = red[0]; __syncthreads();

    float e[4], sum = 0.f;
#pragma unroll
    for (int j = 0; j < 4; j++) {
        int i = t + j * 256;
        e[j] = (i < n) ? expf(v[j] - m) : 0.f;
        sum += e[j];
    }
    red[t] = sum; __syncthreads();
    for (int o = 128; o > 0; o >>= 1) { if (t < o) red[t] += red[t+o]; __syncthreads(); }
    float inv = 1.f / red[0];
#pragma unroll
    for (int j = 0; j < 4; j++) {
        int i = t + j * 256;
        split2(e[j] * inv, prh + i, prl + i);
    }
}

__global__ void oresh_k(const float* __restrict__ o, __half* __restrict__ oh, __half* __restrict__ ol)
{
    int idx = blockIdx.x * blockDim.x + threadIdx.x;   // kBH*kS*kD
    int bh = idx / (kS * kD), rem = idx % (kS * kD);
    int s = rem >> 6, d = rem & 63, b = bh / kH, h = bh % kH;
    size_t dst = ((size_t)(b * kS + s) << 10) + (h << 6) + d;
    split2(o[idx], oh + dst, ol + dst);
}

__global__ void split_k(const float* __restrict__ x, __half* __restrict__ h, __half* __restrict__ l)
{
    int i = blockIdx.x * blockDim.x + threadIdx.x;
    split2(x[i], h + i, l + i);
}

__global__ void rmsnorm_k(const float* __restrict__ x, const float* __restrict__ w,
                          __half* __restrict__ yh, __half* __restrict__ yl)
{
    const int r = blockIdx.x, t = threadIdx.x;
    const float* xr = x + (size_t)r * kE;
    __shared__ float red[256];
    float sum = 0.f;
    for (int i = t; i < kE; i += 256) { float v = xr[i]; sum += v * v; }
    red[t] = sum; __syncthreads();
    for (int o = 128; o > 0; o >>= 1) { if (t < o) red[t] += red[t+o]; __syncthreads(); }
    float rs = rsqrtf(red[0] / kE + 1.1920929e-7f);
    for (int i = t; i < kE; i += 256) {
        size_t o = (size_t)r * kE + i;
        split2(xr[i] * rs * w[i], yh + o, yl + o);
    }
}

__global__ void elumul_k(const float* __restrict__ u, const float* __restrict__ g,
                         __half* __restrict__ uh, __half* __restrict__ ul)
{
    int i = blockIdx.x * blockDim.x + threadIdx.x;
    float gv = g[i];
    split2(u[i] * (gv > 0.f ? gv : expm1f(gv)), uh + i, ul + i);
}

// ------------------------- host launcher -------------------------
#define SYM(p, s) cudaGetSymbolAddress((void**)&p, s)

extern "C" void kernel_launch(void* const* d_in, const int* in_sizes, int n_in,
                              void* d_out, int out_size)
{
    (void)in_sizes; (void)n_in; (void)out_size;
    const int*   tokens = (const int*)  d_in[0];
    const float* table = (const float*)d_in[1];
    const float *Wq = (const float*)d_in[2], *Wk = (const float*)d_in[3], *Wv = (const float*)d_in[4];
    const float *Wproj = (const float*)d_in[5], *normw = (const float*)d_in[6];
    const float *Wup = (const float*)d_in[7], *Wgate = (const float*)d_in[8], *Wdown = (const float*)d_in[9];
    const float *predW = (const float*)d_in[10], *predB = (const float*)d_in[11];
    float* logits = (float*)d_out;

    float *emb, *qkv, *sc, *o, *u, *g, *ct, *st;
    __half *eh, *el, *wqkvh, *wqkvl, *qh, *ql, *kh, *kl, *vth, *vtl, *ph, *pl;
    __half *o2h, *o2l, *wph, *wpl, *wuh, *wul, *wgh, *wgl, *wdh, *wdl, *hh, *hl, *uh, *ul, *pwh, *pwl;
    SYM(emb, g_emb); SYM(qkv, g_qkv); SYM(sc, g_sc); SYM(o, g_o); SYM(u, g_u); SYM(g, g_g);
    SYM(ct, g_ct); SYM(st, g_st);
    SYM(eh, g_eh); SYM(el, g_el); SYM(wqkvh, g_wqkvh); SYM(wqkvl, g_wqkvl);
    SYM(qh, g_qh); SYM(ql, g_ql); SYM(kh, g_kh); SYM(kl, g_kl);
    SYM(vth, g_vth); SYM(vtl, g_vtl); SYM(ph, g_ph); SYM(pl, g_pl);
    SYM(o2h, g_o2h); SYM(o2l, g_o2l); SYM(wph, g_wph); SYM(wpl, g_wpl);
    SYM(wuh, g_wuh); SYM(wul, g_wul); SYM(wgh, g_wgh); SYM(wgl, g_wgl);
    SYM(wdh, g_wdh); SYM(wdl, g_wdl); SYM(hh, g_hh); SYM(hl, g_hl);
    SYM(uh, g_uh); SYM(ul, g_ul); SYM(pwh, g_pwh); SYM(pwl, g_pwl);

    const int SM128 = 2 * (2 * 128 * 144 + 2 * 128 * 144);  // 147456
    const int SM64  = 2 * (2 * 128 * 144 + 2 * 64 * 144);   // 110592
    cudaFuncSetAttribute(tgemm_k<128,false,false,false,false>, cudaFuncAttributeMaxDynamicSharedMemorySize, SM128);
    cudaFuncSetAttribute(tgemm_k<128,false,false,true ,false>, cudaFuncAttributeMaxDynamicSharedMemorySize, SM128);
    cudaFuncSetAttribute(tgemm_k<128,true ,false,false,false>, cudaFuncAttributeMaxDynamicSharedMemorySize, SM128);
    cudaFuncSetAttribute(tgemm_k<128,false,true ,false,false>, cudaFuncAttributeMaxDynamicSharedMemorySize, SM128);
    cudaFuncSetAttribute(tgemm_k<64 ,false,false,false,true >, cudaFuncAttributeMaxDynamicSharedMemorySize, SM64);

    embed_k <<<kBS * kE / 256, 256>>>(tokens, table, emb, eh, el);
    costab_k<<<kS * kD / 256, 256>>>(ct, st);

    for (int l = 0; l < 4; l++) {
        const float* wq = Wq    + (size_t)l * kH * kE * kD;
        const float* wk = Wk    + (size_t)l * kH * kE * kD;
        const float* wv = Wv    + (size_t)l * kH * kE * kD;
        const float* wp = Wproj + (size_t)l * kE * kE;
        const float* nw = normw + (size_t)l * kE;
        const float* wu = Wup   + (size_t)l * kE * kF;
        const float* wg = Wgate + (size_t)l * kE * kF;
        const float* wd = Wdown + (size_t)l * kF * kE;

        // QKV: [2048,1024] x [3072,1024]^T
        wqkv_k<<<kQKV * kE / 256, 256>>>(wq, wk, wv, wqkvh, wqkvl);
        tgemm_k<128,false,false,false,false><<<dim3(kQKV/128, kBS/128), 256, SM128>>>(
            eh, el, kE, 0, wqkvh, wqkvl, kE, 0, qkv, kQKV, 0, nullptr, 1.f, kE);
        rope_k<<<kBS * kQKV / 256, 256>>>(qkv, ct, st, qh, ql, kh, kl, vth, vtl);

        // scores = q @ k^T / 8 (causal tile-skip)
        tgemm_k<128,false,false,true,false><<<dim3(kS/128, kS/128, kBH), 256, SM128>>>(
            qh, ql, kD, (long long)kS*kD, kh, kl, kD, (long long)kS*kD,
            sc, kS, (long long)kS*kS, nullptr, 0.125f, kD);
        softmax_k<<<kBH * kS, 256>>>(sc, ph, pl);

        // o = P @ V (causal K-bound)
        tgemm_k<64,false,false,false,true><<<dim3(1, kS/128, kBH), 256, SM64>>>(
            ph, pl, kS, (long long)kS*kS, vth, vtl, kS, (long long)kD*kS,
            o, kD, (long long)kS*kD, nullptr, 1.f, kS);
        oresh_k<<<kBH * kS * kD / 256, 256>>>(o, o2h, o2l);

        // emb += o2 @ Wproj
        wtr_k<<<dim3(kE/32, kE/32), dim3(32,8)>>>(wp, wph, wpl, kE, kE);
        tgemm_k<128,true,false,false,false><<<dim3(kE/128, kBS/128), 256, SM128>>>(
            o2h, o2l, kE, 0, wph, wpl, kE, 0, emb, kE, 0, nullptr, 1.f, kE);

        // MLP
        rmsnorm_k<<<kBS, 256>>>(emb, nw, hh, hl);
        wtr_k<<<dim3(kF/32, kE/32), dim3(32,8)>>>(wu, wuh, wul, kE, kF);
        wtr_k<<<dim3(kF/32, kE/32), dim3(32,8)>>>(wg, wgh, wgl, kE, kF);
        tgemm_k<128,false,false,false,false><<<dim3(kF/128, kBS/128), 256, SM128>>>(
            hh, hl, kE, 0, wuh, wul, kE, 0, u, kF, 0, nullptr, 1.f, kE);
        tgemm_k<128,false,false,false,false><<<dim3(kF/128, kBS/128), 256, SM128>>>(
            hh, hl, kE, 0, wgh, wgl, kE, 0, g, kF, 0, nullptr, 1.f, kE);
        elumul_k<<<kBS * kF / 256, 256>>>(u, g, uh, ul);
        wtr_k<<<dim3(kE/32, kF/32), dim3(32,8)>>>(wd, wdh, wdl, kF, kE);
        tgemm_k<128,true,false,false,false><<<dim3(kE/128, kBS/128), 256, SM128>>>(
            uh, ul, kF, 0, wdh, wdl, kF, 0, emb, kE, 0, nullptr, 1.f, kF);
        split_k<<<kBS * kE / 256, 256>>>(emb, eh, el);
    }

    // logits = emb @ predW + predB : [2048,1024] x [32000,1024]^T
    wtr_k<<<dim3(kV/32, kE/32), dim3(32,8)>>>(predW, pwh, pwl, kE, kV);
    tgemm_k<128,false,true,false,false><<<dim3(kV/128, kBS/128), 256, SM128>>>(
        eh, el, kE, 0, pwh, pwl, kE, 0, logits, kV, 0, predB, 1.f, kE);
}

// round 7
// speedup vs baseline: 2.4306x; 1.0191x over previous
#include <cuda_runtime.h>
#include <cuda_fp16.h>
#include <math.h>
#include <stdint.h>

namespace {
constexpr int kB = 2, kS = 1024, kE = 1024, kH = 16, kD = 64, kF = 4096, kV = 32000;
constexpr int kBS = kB * kS, kBH = kB * kH, kQKV = 3 * kE;
}

// ------------------------- device scratch -------------------------
__device__ float  g_emb [kBS * kE];
__device__ float  g_qkv [kBS * kQKV];
__device__ float  g_sc  [(size_t)kBH * kS * kS];
__device__ float  g_o   [kBH * kS * kD];
__device__ float  g_u   [kBS * kF];
__device__ float  g_g   [kBS * kF];
__device__ float  g_ct  [kS * kD];
__device__ float  g_st  [kS * kD];

__device__ __half g_eh[kBS*kE], g_el[kBS*kE];
__device__ __half g_wqkvh[kQKV*kE], g_wqkvl[kQKV*kE];
__device__ __half g_qh[kBH*kS*kD], g_ql[kBH*kS*kD];
__device__ __half g_kh[kBH*kS*kD], g_kl[kBH*kS*kD];
__device__ __half g_vth[kBH*kD*kS], g_vtl[kBH*kD*kS];
__device__ __half g_ph[(size_t)kBH*kS*kS], g_pl[(size_t)kBH*kS*kS];
__device__ __half g_o2h[kBS*kE], g_o2l[kBS*kE];
__device__ __half g_wph[kE*kE],  g_wpl[kE*kE];
__device__ __half g_wuh[kF*kE],  g_wul[kF*kE];
__device__ __half g_wgh[kF*kE],  g_wgl[kF*kE];
__device__ __half g_wdh[kE*kF],  g_wdl[kE*kF];
__device__ __half g_hh[kBS*kE],  g_hl[kBS*kE];
__device__ __half g_uh[kBS*kF],  g_ul[kBS*kF];
__device__ __half g_pwh[(size_t)kV*kE], g_pwl[(size_t)kV*kE];

// ------------------------- PTX helpers -------------------------
__device__ __forceinline__ uint32_t smem_u32(const void* p) {
    uint32_t a;
    asm("{ .reg .u64 t; cvta.to.shared.u64 t, %1; cvt.u32.u64 %0, t; }" : "=r"(a) : "l"(p));
    return a;
}
__device__ __forceinline__ void cpasync16(uint32_t dst, const void* src) {
    asm volatile("cp.async.cg.shared.global [%0], [%1], 16;" :: "r"(dst), "l"(src));
}
#define CP_COMMIT() asm volatile("cp.async.commit_group;" ::: "memory")
#define CP_WAIT0()  asm volatile("cp.async.wait_group 0;" ::: "memory")

__device__ __forceinline__ void ldsm4(uint32_t* r, uint32_t addr) {
    asm volatile("ldmatrix.sync.aligned.m8n8.x4.shared.b16 {%0,%1,%2,%3}, [%4];"
        : "=r"(r[0]), "=r"(r[1]), "=r"(r[2]), "=r"(r[3]) : "r"(addr));
}
__device__ __forceinline__ void hmma(float* c, const uint32_t* a, const uint32_t* b) {
    asm volatile("mma.sync.aligned.m16n8k16.row.col.f32.f16.f16.f32 "
        "{%0,%1,%2,%3}, {%4,%5,%6,%7}, {%8,%9}, {%0,%1,%2,%3};"
        : "+f"(c[0]), "+f"(c[1]), "+f"(c[2]), "+f"(c[3])
        : "r"(a[0]), "r"(a[1]), "r"(a[2]), "r"(a[3]), "r"(b[0]), "r"(b[1]));
}
// fp16-accumulate variant (2 regs, 4 packed halves) for the cross-term acc
__device__ __forceinline__ void hmma16(uint32_t* c, const uint32_t* a, const uint32_t* b) {
    asm volatile("mma.sync.aligned.m16n8k16.row.col.f16.f16.f16.f16 "
        "{%0,%1}, {%2,%3,%4,%5}, {%6,%7}, {%0,%1};"
        : "+r"(c[0]), "+r"(c[1])
        : "r"(a[0]), "r"(a[1]), "r"(a[2]), "r"(a[3]), "r"(b[0]), "r"(b[1]));
}
__device__ __forceinline__ void split2(float v, __half* h, __half* l) {
    __half hi = __float2half(v);
    *h = hi;
    *l = __float2half((v - __half2float(hi)) * 1024.f);
}

// stage one ROWS x 64 fp16 tile into 176B-padded smem rows (conflict-free ldsm)
template<int ROWS, int TPB>
__device__ __forceinline__ void stage_cp(uint32_t dst, const __half* __restrict__ src,
                                         long long ld, int k0, int tid)
{
#pragma unroll
    for (int it = 0; it < ROWS * 8 / TPB; it++) {
        int i = it * TPB + tid;
        int r = i >> 3, c = i & 7;
        cpasync16(dst + r * 176 + c * 16, src + (long long)r * ld + k0 + c * 8);
    }
}

// ------------------------- HMMA GEMM -------------------------
// C[M,N] = alpha * (A @ B^T) (+bias[n]) (+C). A:[M,K] hi/lo fp16 K-major,
// B:[N,K] hi/lo fp16 K-major. BM=128, BK=64, 512 threads (4x4 warp grid,
// 32x32 warp tiles), 2-stage cp.async pipeline, one barrier per chunk.
// acc1 (Ah*Bh) in fp32; acc2 (Ah*Bl + Al*Bh) in fp16 accumulate, combined
// as acc1 + acc2/1024 (lo pre-scaled by 1024).
// CAUSAL: skip tiles above diagonal. CAUSK: clamp K at (by+1)*128.
template<int BN, bool ACCUM, bool BIAS, bool CAUSAL, bool CAUSK>
__global__ void __launch_bounds__(512, 1)
tgemm_k(const __half* __restrict__ Ah, const __half* __restrict__ Al, int lda, long long sA,
        const __half* __restrict__ Bh, const __half* __restrict__ Bl, int ldb, long long sB,
        float* __restrict__ C, int ldc, long long sC,
        const float* __restrict__ bias, float alpha, int K)
{
    constexpr int BM = 128, BK = 64, TPB = 512;
    constexpr int WM = 4, WN = 4;               // 16 warps
    constexpr int MT = BM / (WM * 16);          // 2
    constexpr int NT = BN / (WN * 8);           // 4 (BN=128) or 2 (BN=64)
    constexpr int TILEA = BM * 176;
    constexpr int TILEB = BN * 176;
    constexpr int STAGE = 2 * TILEA + 2 * TILEB;

    const int bx = blockIdx.x, by = blockIdx.y, bz = blockIdx.z;
    if (CAUSAL && bx * BN > by * BM + BM - 1) return;
    int Ktot = K;
    if (CAUSK) { int km = (by + 1) * BM; if (km < Ktot) Ktot = km; }
    const int NC = Ktot / BK;

    extern __shared__ char sm[];
    const uint32_t sb = smem_u32(sm);
    const int tid = threadIdx.x, lane = tid & 31, wid = tid >> 5;
    const int m0 = (wid / WN) * MT * 16;
    const int n0 = (wid % WN) * NT * 8;

    const __half* pAh = Ah + bz * sA + (long long)by * BM * lda;
    const __half* pAl = Al + bz * sA + (long long)by * BM * lda;
    const __half* pBh = Bh + bz * sB + (long long)bx * BN * ldb;
    const __half* pBl = Bl + bz * sB + (long long)bx * BN * ldb;

    float    acc1[MT][NT][4];
    uint32_t acc2[MT][NT][2];
#pragma unroll
    for (int mt = 0; mt < MT; mt++)
#pragma unroll
        for (int nt = 0; nt < NT; nt++) {
#pragma unroll
            for (int i = 0; i < 4; i++) acc1[mt][nt][i] = 0.f;
            acc2[mt][nt][0] = 0u; acc2[mt][nt][1] = 0u;
        }

    auto stage_all = [&](int buf, int k0) {
        uint32_t s0 = sb + (uint32_t)buf * STAGE;
        stage_cp<BM, TPB>(s0,                    pAh, lda, k0, tid);
        stage_cp<BM, TPB>(s0 + TILEA,            pAl, lda, k0, tid);
        stage_cp<BN, TPB>(s0 + 2*TILEA,          pBh, ldb, k0, tid);
        stage_cp<BN, TPB>(s0 + 2*TILEA + TILEB,  pBl, ldb, k0, tid);
    };

    stage_all(0, 0); CP_COMMIT();

    for (int i = 0; i < NC; i++) {
        CP_WAIT0();
        __syncthreads();
        if (i + 1 < NC) { stage_all((i + 1) & 1, (i + 1) * BK); CP_COMMIT(); }

        const uint32_t s0 = sb + (uint32_t)(i & 1) * STAGE;
        const uint32_t aH = s0, aL = s0 + TILEA;
        const uint32_t bH = s0 + 2*TILEA, bL = s0 + 2*TILEA + TILEB;

#pragma unroll
        for (int ks = 0; ks < 4; ks++) {
            const int kc = ks * 2;
            uint32_t ah[MT][4], al[MT][4], bhf[NT][2], blf[NT][2];

#pragma unroll
            for (int nt = 0; nt < NT; nt += 2) {
                const int g = lane >> 3;
                const uint32_t off =
                    (uint32_t)(n0 + nt * 8 + ((g >> 1) << 3) + (lane & 7)) * 176
                    + (uint32_t)(kc + (g & 1)) * 16;
                uint32_t r[4];
                ldsm4(r, bH + off);
                bhf[nt][0] = r[0]; bhf[nt][1] = r[1];
                bhf[nt+1][0] = r[2]; bhf[nt+1][1] = r[3];
                ldsm4(r, bL + off);
                blf[nt][0] = r[0]; blf[nt][1] = r[1];
                blf[nt+1][0] = r[2]; blf[nt+1][1] = r[3];
            }
#pragma unroll
            for (int mt = 0; mt < MT; mt++) {
                const uint32_t off =
                    (uint32_t)(m0 + mt * 16 + (lane & 15)) * 176
                    + (uint32_t)(kc + (lane >> 4)) * 16;
                ldsm4(ah[mt], aH + off);
                ldsm4(al[mt], aL + off);
            }
#pragma unroll
            for (int mt = 0; mt < MT; mt++)
#pragma unroll
                for (int nt = 0; nt < NT; nt++) {
                    hmma  (acc1[mt][nt], ah[mt], bhf[nt]);
                    hmma16(acc2[mt][nt], ah[mt], blf[nt]);
                    hmma16(acc2[mt][nt], al[mt], bhf[nt]);
                }
        }
    }

    // ---- epilogue ----
    const float inv = 1.f / 1024.f;
    float* Cp = C + bz * sC;
#pragma unroll
    for (int mt = 0; mt < MT; mt++) {
#pragma unroll
        for (int nt = 0; nt < NT; nt++) {
            const int row = by * BM + m0 + mt * 16 + (lane >> 2);
            const int col = bx * BN + n0 + nt * 8 + ((lane & 3) << 1);
#pragma unroll
            for (int h = 0; h < 2; h++) {
                const int r = row + h * 8;
                __half2 c2 = *reinterpret_cast<__half2*>(&acc2[mt][nt][h]);
                float v0 = (acc1[mt][nt][2*h]   + __low2float(c2)  * inv) * alpha;
                float v1 = (acc1[mt][nt][2*h+1] + __high2float(c2) * inv) * alpha;
                if (BIAS) { v0 += bias[col]; v1 += bias[col + 1]; }
                float2* p = reinterpret_cast<float2*>(Cp + (long long)r * ldc + col);
                if (ACCUM) { float2 o = *p; v0 += o.x; v1 += o.y; }
                *p = make_float2(v0, v1);
            }
        }
    }
}

// ------------------------- elementwise kernels -------------------------
__global__ void embed_k(const int* __restrict__ tok, const float* __restrict__ tab,
                        float* __restrict__ out, __half* __restrict__ eh, __half* __restrict__ el)
{
    int idx = blockIdx.x * blockDim.x + threadIdx.x;
    float v = tab[(size_t)tok[idx >> 10] * kE + (idx & 1023)];
    out[idx] = v; split2(v, eh + idx, el + idx);
}

__global__ void costab_k(float* __restrict__ ct, float* __restrict__ st)
{
    int idx = blockIdx.x * blockDim.x + threadIdx.x;
    int s = idx / kD, i = idx % kD;
    float theta = powf(10000.f, (-2.f / kD) * (float)(i & 31));
    ct[idx] = cosf((float)s * theta);
    st[idx] = sinf((float)s * theta) * (i < kD/2 ? -1.f : 1.f);
}

__global__ void wqkv_k(const float* __restrict__ wq, const float* __restrict__ wk,
                       const float* __restrict__ wv, __half* __restrict__ h, __half* __restrict__ l)
{
    int idx = blockIdx.x * blockDim.x + threadIdx.x;   // kQKV*kE
    int n = idx / kE, e = idx % kE;
    int seg = n >> 10, hh = (n & 1023) >> 6, k = n & 63;
    const float* w = seg == 0 ? wq : seg == 1 ? wk : wv;
    split2(w[((size_t)hh * kE + e) * kD + k], h + idx, l + idx);
}

__global__ void wtr_k(const float* __restrict__ src, __half* __restrict__ dh,
                      __half* __restrict__ dl, int K, int N)
{
    __shared__ float t[32][33];
    int k0 = blockIdx.y * 32, n0 = blockIdx.x * 32;
    for (int r = threadIdx.y; r < 32; r += 8)
        t[r][threadIdx.x] = src[(size_t)(k0 + r) * N + n0 + threadIdx.x];
    __syncthreads();
    for (int r = threadIdx.y; r < 32; r += 8) {
        size_t o = (size_t)(n0 + r) * K + k0 + threadIdx.x;
        split2(t[threadIdx.x][r], dh + o, dl + o);
    }
}

__global__ void rope_k(const float* __restrict__ qkv, const float* __restrict__ ct,
                       const float* __restrict__ st,
                       __half* __restrict__ qh, __half* __restrict__ ql,
                       __half* __restrict__ kh, __half* __restrict__ kl,
                       __half* __restrict__ vth, __half* __restrict__ vtl)
{
    int idx = blockIdx.x * blockDim.x + threadIdx.x;   // kBS*kQKV
    int row = idx / kQKV, c = idx % kQKV;
    int b = row >> 10, s = row & 1023;
    int seg = c >> 10, h = (c & 1023) >> 6, i = c & 63;
    float x = qkv[idx];
    if (seg == 2) {
        size_t dst = ((size_t)(b * kH + h) * kD + i) * kS + s;
        split2(x, vth + dst, vtl + dst);
        return;
    }
    float sw = qkv[(size_t)row * kQKV + (seg << 10) + (h << 6) + ((i + 32) & 63)];
    float val = ct[(s << 6) + i] * x + st[(s << 6) + i] * sw;
    size_t dst = ((size_t)(b * kH + h) * kS + s) * kD + i;
    if (seg == 0) split2(val, qh + dst, ql + dst);
    else          split2(val, kh + dst, kl + dst);
}

// register-resident causal softmax: 256 threads, 4 cols/thread
__global__ void softmax_k(const float* __restrict__ sc,
                          __half* __restrict__ ph, __half* __restrict__ pl)
{
    const int r = blockIdx.x, s = r & (kS - 1), n = s + 1, t = threadIdx.x;
    const float* row = sc + (size_t)r * kS;
    __half* prh = ph + (size_t)r * kS;
    __half* prl = pl + (size_t)r * kS;
    __shared__ float red[256];

    float v[4];
#pragma unroll
    for (int j = 0; j < 4; j++) {
        int i = t + j * 256;
        v[j] = (i < n) ? row[i] : -INFINITY;
    }
    float m = fmaxf(fmaxf(v[0], v[1]), fmaxf(v[2], v[3]));
    red[t] = m; __syncthreads();
    for (int o = 128; o > 0; o >>= 1) { if (t < o) red[t] = fmaxf(red[t], red[t+o]); __syncthreads(); }
    m = red[0]; __syncthreads();

    float e[4], sum = 0.f;
#pragma unroll
    for (int j = 0; j < 4; j++) {
        int i = t + j * 256;
        e[j] = (i < n) ? expf(v[j] - m) : 0.f;
        sum += e[j];
    }
    red[t] = sum; __syncthreads();
    for (int o = 128; o > 0; o >>= 1) { if (t < o) red[t] += red[t+o]; __syncthreads(); }
    float inv = 1.f / red[0];
#pragma unroll
    for (int j = 0; j < 4; j++) {
        int i = t + j * 256;
        split2(e[j] * inv, prh + i, prl + i);
    }
}

__global__ void oresh_k(const float* __restrict__ o, __half* __restrict__ oh, __half* __restrict__ ol)
{
    int idx = blockIdx.x * blockDim.x + threadIdx.x;   // kBH*kS*kD
    int bh = idx / (kS * kD), rem = idx % (kS * kD);
    int s = rem >> 6, d = rem & 63, b = bh / kH, h = bh % kH;
    size_t dst = ((size_t)(b * kS + s) << 10) + (h << 6) + d;
    split2(o[idx], oh + dst, ol + dst);
}

__global__ void split_k(const float* __restrict__ x, __half* __restrict__ h, __half* __restrict__ l)
{
    int i = blockIdx.x * blockDim.x + threadIdx.x;
    split2(x[i], h + i, l + i);
}

__global__ void rmsnorm_k(const float* __restrict__ x, const float* __restrict__ w,
                          __half* __restrict__ yh, __half* __restrict__ yl)
{
    const int r = blockIdx.x, t = threadIdx.x;
    const float* xr = x + (size_t)r * kE;
    __shared__ float red[256];
    float sum = 0.f;
    for (int i = t; i < kE; i += 256) { float v = xr[i]; sum += v * v; }
    red[t] = sum; __syncthreads();
    for (int o = 128; o > 0; o >>= 1) { if (t < o) red[t] += red[t+o]; __syncthreads(); }
    float rs = rsqrtf(red[0] / kE + 1.1920929e-7f);
    for (int i = t; i < kE; i += 256) {
        size_t o = (size_t)r * kE + i;
        split2(xr[i] * rs * w[i], yh + o, yl + o);
    }
}

__global__ void elumul_k(const float* __restrict__ u, const float* __restrict__ g,
                         __half* __restrict__ uh, __half* __restrict__ ul)
{
    int i = blockIdx.x * blockDim.x + threadIdx.x;
    float gv = g[i];
    split2(u[i] * (gv > 0.f ? gv : expm1f(gv)), uh + i, ul + i);
}

// ------------------------- host launcher -------------------------
#define SYM(p, s) cudaGetSymbolAddress((void**)&p, s)

extern "C" void kernel_launch(void* const* d_in, const int* in_sizes, int n_in,
                              void* d_out, int out_size)
{
    (void)in_sizes; (void)n_in; (void)out_size;
    const int*   tokens = (const int*)  d_in[0];
    const float* table = (const float*)d_in[1];
    const float *Wq = (const float*)d_in[2], *Wk = (const float*)d_in[3], *Wv = (const float*)d_in[4];
    const float *Wproj = (const float*)d_in[5], *normw = (const float*)d_in[6];
    const float *Wup = (const float*)d_in[7], *Wgate = (const float*)d_in[8], *Wdown = (const float*)d_in[9];
    const float *predW = (const float*)d_in[10], *predB = (const float*)d_in[11];
    float* logits = (float*)d_out;

    float *emb, *qkv, *sc, *o, *u, *g, *ct, *st;
    __half *eh, *el, *wqkvh, *wqkvl, *qh, *ql, *kh, *kl, *vth, *vtl, *ph, *pl;
    __half *o2h, *o2l, *wph, *wpl, *wuh, *wul, *wgh, *wgl, *wdh, *wdl, *hh, *hl, *uh, *ul, *pwh, *pwl;
    SYM(emb, g_emb); SYM(qkv, g_qkv); SYM(sc, g_sc); SYM(o, g_o); SYM(u, g_u); SYM(g, g_g);
    SYM(ct, g_ct); SYM(st, g_st);
    SYM(eh, g_eh); SYM(el, g_el); SYM(wqkvh, g_wqkvh); SYM(wqkvl, g_wqkvl);
    SYM(qh, g_qh); SYM(ql, g_ql); SYM(kh, g_kh); SYM(kl, g_kl);
    SYM(vth, g_vth); SYM(vtl, g_vtl); SYM(ph, g_ph); SYM(pl, g_pl);
    SYM(o2h, g_o2h); SYM(o2l, g_o2l); SYM(wph, g_wph); SYM(wpl, g_wpl);
    SYM(wuh, g_wuh); SYM(wul, g_wul); SYM(wgh, g_wgh); SYM(wgl, g_wgl);
    SYM(wdh, g_wdh); SYM(wdl, g_wdl); SYM(hh, g_hh); SYM(hl, g_hl);
    SYM(uh, g_uh); SYM(ul, g_ul); SYM(pwh, g_pwh); SYM(pwl, g_pwl);

    const int SM128 = 2 * (2 * 128 * 176 + 2 * 128 * 176);  // 180224
    const int SM64  = 2 * (2 * 128 * 176 + 2 * 64 * 176);   // 135168
    cudaFuncSetAttribute(tgemm_k<128,false,false,false,false>, cudaFuncAttributeMaxDynamicSharedMemorySize, SM128);
    cudaFuncSetAttribute(tgemm_k<128,false,false,true ,false>, cudaFuncAttributeMaxDynamicSharedMemorySize, SM128);
    cudaFuncSetAttribute(tgemm_k<128,true ,false,false,false>, cudaFuncAttributeMaxDynamicSharedMemorySize, SM128);
    cudaFuncSetAttribute(tgemm_k<128,false,true ,false,false>, cudaFuncAttributeMaxDynamicSharedMemorySize, SM128);
    cudaFuncSetAttribute(tgemm_k<64 ,false,false,false,true >, cudaFuncAttributeMaxDynamicSharedMemorySize, SM64);

    embed_k <<<kBS * kE / 256, 256>>>(tokens, table, emb, eh, el);
    costab_k<<<kS * kD / 256, 256>>>(ct, st);

    for (int l = 0; l < 4; l++) {
        const float* wq = Wq    + (size_t)l * kH * kE * kD;
        const float* wk = Wk    + (size_t)l * kH * kE * kD;
        const float* wv = Wv    + (size_t)l * kH * kE * kD;
        const float* wp = Wproj + (size_t)l * kE * kE;
        const float* nw = normw + (size_t)l * kE;
        const float* wu = Wup   + (size_t)l * kE * kF;
        const float* wg = Wgate + (size_t)l * kE * kF;
        const float* wd = Wdown + (size_t)l * kF * kE;

        // QKV: [2048,1024] x [3072,1024]^T
        wqkv_k<<<kQKV * kE / 256, 256>>>(wq, wk, wv, wqkvh, wqkvl);
        tgemm_k<128,false,false,false,false><<<dim3(kQKV/128, kBS/128), 512, SM128>>>(
            eh, el, kE, 0, wqkvh, wqkvl, kE, 0, qkv, kQKV, 0, nullptr, 1.f, kE);
        rope_k<<<kBS * kQKV / 256, 256>>>(qkv, ct, st, qh, ql, kh, kl, vth, vtl);

        // scores = q @ k^T / 8 (causal tile-skip)
        tgemm_k<128,false,false,true,false><<<dim3(kS/128, kS/128, kBH), 512, SM128>>>(
            qh, ql, kD, (long long)kS*kD, kh, kl, kD, (long long)kS*kD,
            sc, kS, (long long)kS*kS, nullptr, 0.125f, kD);
        softmax_k<<<kBH * kS, 256>>>(sc, ph, pl);

        // o = P @ V (causal K-bound)
        tgemm_k<64,false,false,false,true><<<dim3(1, kS/128, kBH), 512, SM64>>>(
            ph, pl, kS, (long long)kS*kS, vth, vtl, kS, (long long)kD*kS,
            o, kD, (long long)kS*kD, nullptr, 1.f, kS);
        oresh_k<<<kBH * kS * kD / 256, 256>>>(o, o2h, o2l);

        // emb += o2 @ Wproj
        wtr_k<<<dim3(kE/32, kE/32), dim3(32,8)>>>(wp, wph, wpl, kE, kE);
        tgemm_k<128,true,false,false,false><<<dim3(kE/128, kBS/128), 512, SM128>>>(
            o2h, o2l, kE, 0, wph, wpl, kE, 0, emb, kE, 0, nullptr, 1.f, kE);

        // MLP
        rmsnorm_k<<<kBS, 256>>>(emb, nw, hh, hl);
        wtr_k<<<dim3(kF/32, kE/32), dim3(32,8)>>>(wu, wuh, wul, kE, kF);
        wtr_k<<<dim3(kF/32, kE/32), dim3(32,8)>>>(wg, wgh, wgl, kE, kF);
        tgemm_k<128,false,false,false,false><<<dim3(kF/128, kBS/128), 512, SM128>>>(
            hh, hl, kE, 0, wuh, wul, kE, 0, u, kF, 0, nullptr, 1.f, kE);
        tgemm_k<128,false,false,false,false><<<dim3(kF/128, kBS/128), 512, SM128>>>(
            hh, hl, kE, 0, wgh, wgl, kE, 0, g, kF, 0, nullptr, 1.f, kE);
        elumul_k<<<kBS * kF / 256, 256>>>(u, g, uh, ul);
        wtr_k<<<dim3(kE/32, kF/32), dim3(32,8)>>>(wd, wdh, wdl, kF, kE);
        tgemm_k<128,true,false,false,false><<<dim3(kE/128, kBS/128), 512, SM128>>>(
            uh, ul, kF, 0, wdh, wdl, kF, 0, emb, kE, 0, nullptr, 1.f, kF);
        split_k<<<kBS * kE / 256, 256>>>(emb, eh, el);
    }

    // logits = emb @ predW + predB : [2048,1024] x [32000,1024]^T
    wtr_k<<<dim3(kV/32, kE/32), dim3(32,8)>>>(predW, pwh, pwl, kE, kV);
    tgemm_k<128,false,true,false,false><<<dim3(kV/128, kBS/128), 512, SM128>>>(
        eh, el, kE, 0, pwh, pwl, kE, 0, logits, kV, 0, predB, 1.f, kE);
}

// round 9
// speedup vs baseline: 2.7656x; 1.1378x over previous
#include <cuda_runtime.h>
#include <cuda_fp16.h>
#include <math.h>
#include <stdint.h>

namespace {
constexpr int kB = 2, kS = 1024, kE = 1024, kH = 16, kD = 64, kF = 4096, kV = 32000;
constexpr int kBS = kB * kS, kBH = kB * kH, kQKV = 3 * kE;
}

// ------------------------- device scratch -------------------------
__device__ float  g_emb [kBS * kE];
__device__ float  g_qkv [kBS * kQKV];
__device__ float  g_sc  [(size_t)kBH * kS * kS];
__device__ float  g_o   [kBH * kS * kD];
__device__ float  g_u   [kBS * kF];
__device__ float  g_g   [kBS * kF];
__device__ float  g_ct  [kS * kD];
__device__ float  g_st  [kS * kD];

__device__ __half g_eh[kBS*kE], g_el[kBS*kE];
__device__ __half g_wqkvh[kQKV*kE], g_wqkvl[kQKV*kE];
__device__ __half g_qh[kBH*kS*kD], g_ql[kBH*kS*kD];
__device__ __half g_kh[kBH*kS*kD], g_kl[kBH*kS*kD];
__device__ __half g_vth[kBH*kD*kS], g_vtl[kBH*kD*kS];
__device__ __half g_ph[(size_t)kBH*kS*kS], g_pl[(size_t)kBH*kS*kS];
__device__ __half g_o2h[kBS*kE], g_o2l[kBS*kE];
__device__ __half g_wph[kE*kE],  g_wpl[kE*kE];
__device__ __half g_wuh[kF*kE],  g_wul[kF*kE];
__device__ __half g_wgh[kF*kE],  g_wgl[kF*kE];
__device__ __half g_wdh[kE*kF],  g_wdl[kE*kF];
__device__ __half g_hh[kBS*kE],  g_hl[kBS*kE];
__device__ __half g_uh[kBS*kF],  g_ul[kBS*kF];
__device__ __half g_pwh[(size_t)kV*kE];

// ------------------------- PTX helpers -------------------------
__device__ __forceinline__ uint32_t smem_u32(const void* p) {
    uint32_t a;
    asm("{ .reg .u64 t; cvta.to.shared.u64 t, %1; cvt.u32.u64 %0, t; }" : "=r"(a) : "l"(p));
    return a;
}
__device__ __forceinline__ void cpasync16(uint32_t dst, const void* src) {
    asm volatile("cp.async.cg.shared.global [%0], [%1], 16;" :: "r"(dst), "l"(src));
}
#define CP_COMMIT() asm volatile("cp.async.commit_group;" ::: "memory")
#define CP_WAIT0()  asm volatile("cp.async.wait_group 0;" ::: "memory")

__device__ __forceinline__ void ldsm4(uint32_t* r, uint32_t addr) {
    asm volatile("ldmatrix.sync.aligned.m8n8.x4.shared.b16 {%0,%1,%2,%3}, [%4];"
        : "=r"(r[0]), "=r"(r[1]), "=r"(r[2]), "=r"(r[3]) : "r"(addr));
}
__device__ __forceinline__ void hmma(float* c, const uint32_t* a, const uint32_t* b) {
    asm volatile("mma.sync.aligned.m16n8k16.row.col.f32.f16.f16.f32 "
        "{%0,%1,%2,%3}, {%4,%5,%6,%7}, {%8,%9}, {%0,%1,%2,%3};"
        : "+f"(c[0]), "+f"(c[1]), "+f"(c[2]), "+f"(c[3])
        : "r"(a[0]), "r"(a[1]), "r"(a[2]), "r"(a[3]), "r"(b[0]), "r"(b[1]));
}
__device__ __forceinline__ void hmma16(uint32_t* c, const uint32_t* a, const uint32_t* b) {
    asm volatile("mma.sync.aligned.m16n8k16.row.col.f16.f16.f16.f16 "
        "{%0,%1}, {%2,%3,%4,%5}, {%6,%7}, {%0,%1};"
        : "+r"(c[0]), "+r"(c[1])
        : "r"(a[0]), "r"(a[1]), "r"(a[2]), "r"(a[3]), "r"(b[0]), "r"(b[1]));
}
__device__ __forceinline__ void split2(float v, __half* h, __half* l) {
    __half hi = __float2half(v);
    *h = hi;
    *l = __float2half((v - __half2float(hi)) * 1024.f);
}

// stage one ROWS x 64 fp16 tile into 176B-padded smem rows (conflict-free ldsm)
template<int ROWS, int TPB>
__device__ __forceinline__ void stage_cp(uint32_t dst, const __half* __restrict__ src,
                                         long long ld, int k0, int tid)
{
#pragma unroll
    for (int it = 0; it < ROWS * 8 / TPB; it++) {
        int i = it * TPB + tid;
        int r = i >> 3, c = i & 7;
        cpasync16(dst + r * 176 + c * 16, src + (long long)r * ld + k0 + c * 8);
    }
}

// ------------------------- HMMA GEMM -------------------------
// C[M,N] = alpha * (A @ B^T) (+bias[n]) (+C).
// SPLIT: hi/lo fp16 operands (x = hi + lo/1024); acc1 fp32 Ah*Bh,
//        acc2 fp16 (Ah*Bl + Al*Bh), result acc1 + acc2/1024.
// !SPLIT: single fp16 operands, fp32 accumulate.
// BM=128, BK=64, 512 thr (4x4 warps, 32x32 warp tiles), 2-stage cp.async.
// CAUSAL: skip tiles above diagonal. CAUSK: clamp K at (by+1)*128.
template<int BN, bool SPLIT, bool ACCUM, bool BIAS, bool CAUSAL, bool CAUSK>
__global__ void __launch_bounds__(512, 1)
tgemm_k(const __half* __restrict__ Ah, const __half* __restrict__ Al, int lda, long long sA,
        const __half* __restrict__ Bh, const __half* __restrict__ Bl, int ldb, long long sB,
        float* __restrict__ C, int ldc, long long sC,
        const float* __restrict__ bias, float alpha, int K)
{
    constexpr int BM = 128, BK = 64, TPB = 512;
    constexpr int WM = 4, WN = 4;
    constexpr int MT = BM / (WM * 16);
    constexpr int NT = BN / (WN * 8);
    constexpr int TILEA = BM * 176;
    constexpr int TILEB = BN * 176;
    constexpr int NTILES = SPLIT ? 2 : 1;
    constexpr int STAGE = NTILES * (TILEA + TILEB);

    const int bx = blockIdx.x, by = blockIdx.y, bz = blockIdx.z;
    if (CAUSAL && bx * BN > by * BM + BM - 1) return;
    int Ktot = K;
    if (CAUSK) { int km = (by + 1) * BM; if (km < Ktot) Ktot = km; }
    const int NC = Ktot / BK;

    extern __shared__ char sm[];
    const uint32_t sb = smem_u32(sm);
    const int tid = threadIdx.x, lane = tid & 31, wid = tid >> 5;
    const int m0 = (wid / WN) * MT * 16;
    const int n0 = (wid % WN) * NT * 8;

    const __half* pAh = Ah + bz * sA + (long long)by * BM * lda;
    const __half* pAl = SPLIT ? Al + bz * sA + (long long)by * BM * lda : nullptr;
    const __half* pBh = Bh + bz * sB + (long long)bx * BN * ldb;
    const __half* pBl = SPLIT ? Bl + bz * sB + (long long)bx * BN * ldb : nullptr;

    float    acc1[MT][NT][4];
    uint32_t acc2[MT][NT][2];
#pragma unroll
    for (int mt = 0; mt < MT; mt++)
#pragma unroll
        for (int nt = 0; nt < NT; nt++) {
#pragma unroll
            for (int i = 0; i < 4; i++) acc1[mt][nt][i] = 0.f;
            acc2[mt][nt][0] = 0u; acc2[mt][nt][1] = 0u;
        }

    auto stage_all = [&](int buf, int k0) {
        uint32_t s0 = sb + (uint32_t)buf * STAGE;
        stage_cp<BM, TPB>(s0, pAh, lda, k0, tid);
        stage_cp<BN, TPB>(s0 + NTILES*TILEA, pBh, ldb, k0, tid);
        if (SPLIT) {
            stage_cp<BM, TPB>(s0 + TILEA, pAl, lda, k0, tid);
            stage_cp<BN, TPB>(s0 + NTILES*TILEA + TILEB, pBl, ldb, k0, tid);
        }
    };

    stage_all(0, 0); CP_COMMIT();

    for (int i = 0; i < NC; i++) {
        CP_WAIT0();
        __syncthreads();
        if (i + 1 < NC) { stage_all((i + 1) & 1, (i + 1) * BK); CP_COMMIT(); }

        const uint32_t s0 = sb + (uint32_t)(i & 1) * STAGE;
        const uint32_t aH = s0, aL = s0 + TILEA;
        const uint32_t bH = s0 + NTILES*TILEA, bL = s0 + NTILES*TILEA + TILEB;

#pragma unroll
        for (int ks = 0; ks < 4; ks++) {
            const int kc = ks * 2;
            uint32_t ah[MT][4], al[MT][4], bhf[NT][2], blf[NT][2];

#pragma unroll
            for (int nt = 0; nt < NT; nt += 2) {
                const int g = lane >> 3;
                const uint32_t off =
                    (uint32_t)(n0 + nt * 8 + ((g >> 1) << 3) + (lane & 7)) * 176
                    + (uint32_t)(kc + (g & 1)) * 16;
                uint32_t r[4];
                ldsm4(r, bH + off);
                bhf[nt][0] = r[0]; bhf[nt][1] = r[1];
                bhf[nt+1][0] = r[2]; bhf[nt+1][1] = r[3];
                if (SPLIT) {
                    ldsm4(r, bL + off);
                    blf[nt][0] = r[0]; blf[nt][1] = r[1];
                    blf[nt+1][0] = r[2]; blf[nt+1][1] = r[3];
                }
            }
#pragma unroll
            for (int mt = 0; mt < MT; mt++) {
                const uint32_t off =
                    (uint32_t)(m0 + mt * 16 + (lane & 15)) * 176
                    + (uint32_t)(kc + (lane >> 4)) * 16;
                ldsm4(ah[mt], aH + off);
                if (SPLIT) ldsm4(al[mt], aL + off);
            }
#pragma unroll
            for (int mt = 0; mt < MT; mt++)
#pragma unroll
                for (int nt = 0; nt < NT; nt++) {
                    hmma(acc1[mt][nt], ah[mt], bhf[nt]);
                    if (SPLIT) {
                        hmma16(acc2[mt][nt], ah[mt], blf[nt]);
                        hmma16(acc2[mt][nt], al[mt], bhf[nt]);
                    }
                }
        }
    }

    // ---- epilogue ----
    const float inv = 1.f / 1024.f;
    float* Cp = C + bz * sC;
#pragma unroll
    for (int mt = 0; mt < MT; mt++) {
#pragma unroll
        for (int nt = 0; nt < NT; nt++) {
            const int row = by * BM + m0 + mt * 16 + (lane >> 2);
            const int col = bx * BN + n0 + nt * 8 + ((lane & 3) << 1);
#pragma unroll
            for (int h = 0; h < 2; h++) {
                const int r = row + h * 8;
                float v0 = acc1[mt][nt][2*h], v1 = acc1[mt][nt][2*h+1];
                if (SPLIT) {
                    __half2 c2 = *reinterpret_cast<__half2*>(&acc2[mt][nt][h]);
                    v0 += __low2float(c2) * inv;
                    v1 += __high2float(c2) * inv;
                }
                v0 *= alpha; v1 *= alpha;
                if (BIAS) { v0 += bias[col]; v1 += bias[col + 1]; }
                float2* p = reinterpret_cast<float2*>(Cp + (long long)r * ldc + col);
                if (ACCUM) { float2 o = *p; v0 += o.x; v1 += o.y; }
                *p = make_float2(v0, v1);
            }
        }
    }
}

// ------------------------- elementwise kernels -------------------------
__global__ void embed_k(const int* __restrict__ tok, const float* __restrict__ tab,
                        float* __restrict__ out, __half* __restrict__ eh, __half* __restrict__ el)
{
    int idx = blockIdx.x * blockDim.x + threadIdx.x;
    float v = tab[(size_t)tok[idx >> 10] * kE + (idx & 1023)];
    out[idx] = v; split2(v, eh + idx, el + idx);
}

__global__ void costab_k(float* __restrict__ ct, float* __restrict__ st)
{
    int idx = blockIdx.x * blockDim.x + threadIdx.x;
    int s = idx / kD, i = idx % kD;
    float theta = powf(10000.f, (-2.f / kD) * (float)(i & 31));
    ct[idx] = cosf((float)s * theta);
    st[idx] = sinf((float)s * theta) * (i < kD/2 ? -1.f : 1.f);
}

__global__ void wqkv_k(const float* __restrict__ wq, const float* __restrict__ wk,
                       const float* __restrict__ wv, __half* __restrict__ h, __half* __restrict__ l)
{
    int idx = blockIdx.x * blockDim.x + threadIdx.x;
    int n = idx / kE, e = idx % kE;
    int seg = n >> 10, hh = (n & 1023) >> 6, k = n & 63;
    const float* w = seg == 0 ? wq : seg == 1 ? wk : wv;
    split2(w[((size_t)hh * kE + e) * kD + k], h + idx, l + idx);
}

// src [K,N] fp32 -> dst [N,K] fp16 hi (and lo if dl != nullptr)
__global__ void wtr_k(const float* __restrict__ src, __half* __restrict__ dh,
                      __half* __restrict__ dl, int K, int N)
{
    __shared__ float t[32][33];
    int k0 = blockIdx.y * 32, n0 = blockIdx.x * 32;
    for (int r = threadIdx.y; r < 32; r += 8)
        t[r][threadIdx.x] = src[(size_t)(k0 + r) * N + n0 + threadIdx.x];
    __syncthreads();
    for (int r = threadIdx.y; r < 32; r += 8) {
        size_t o = (size_t)(n0 + r) * K + k0 + threadIdx.x;
        float v = t[threadIdx.x][r];
        if (dl) split2(v, dh + o, dl + o);
        else    dh[o] = __float2half(v);
    }
}

__global__ void rope_k(const float* __restrict__ qkv, const float* __restrict__ ct,
                       const float* __restrict__ st,
                       __half* __restrict__ qh, __half* __restrict__ ql,
                       __half* __restrict__ kh, __half* __restrict__ kl,
                       __half* __restrict__ vth, __half* __restrict__ vtl)
{
    int idx = blockIdx.x * blockDim.x + threadIdx.x;
    int row = idx / kQKV, c = idx % kQKV;
    int b = row >> 10, s = row & 1023;
    int seg = c >> 10, h = (c & 1023) >> 6, i = c & 63;
    float x = qkv[idx];
    if (seg == 2) {
        size_t dst = ((size_t)(b * kH + h) * kD + i) * kS + s;
        split2(x, vth + dst, vtl + dst);
        return;
    }
    float sw = qkv[(size_t)row * kQKV + (seg << 10) + (h << 6) + ((i + 32) & 63)];
    float val = ct[(s << 6) + i] * x + st[(s << 6) + i] * sw;
    size_t dst = ((size_t)(b * kH + h) * kS + s) * kD + i;
    if (seg == 0) split2(val, qh + dst, ql + dst);
    else          split2(val, kh + dst, kl + dst);
}

// register-resident causal softmax: 256 threads, 4 cols/thread
__global__ void softmax_k(const float* __restrict__ sc,
                          __half* __restrict__ ph, __half* __restrict__ pl)
{
    const int r = blockIdx.x, s = r & (kS - 1), n = s + 1, t = threadIdx.x;
    const float* row = sc + (size_t)r * kS;
    __half* prh = ph + (size_t)r * kS;
    __half* prl = pl + (size_t)r * kS;
    __shared__ float red[256];

    float v[4];
#pragma unroll
    for (int j = 0; j < 4; j++) {
        int i = t + j * 256;
        v[j] = (i < n) ? row[i] : -INFINITY;
    }
    float m = fmaxf(fmaxf(v[0], v[1]), fmaxf(v[2], v[3]));
    red[t] = m; __syncthreads();
    for (int o = 128; o > 0; o >>= 1) { if (t < o) red[t] = fmaxf(red[t], red[t+o]); __syncthreads(); }
    m = red[0]; __syncthreads();

    float e[4], sum = 0.f;
#pragma unroll
    for (int j = 0; j < 4; j++) {
        int i = t + j * 256;
        e[j] = (i < n) ? expf(v[j] - m) : 0.f;
        sum += e[j];
    }
    red[t] = sum; __syncthreads();
    for (int o = 128; o > 0; o >>= 1) { if (t < o) red[t] += red[t+o]; __syncthreads(); }
    float inv = 1.f / red[0];
#pragma unroll
    for (int j = 0; j < 4; j++) {
        int i = t + j * 256;
        split2(e[j] * inv, prh + i, prl + i);
    }
}

__global__ void oresh_k(const float* __restrict__ o, __half* __restrict__ oh, __half* __restrict__ ol)
{
    int idx = blockIdx.x * blockDim.x + threadIdx.x;
    int bh = idx / (kS * kD), rem = idx % (kS * kD);
    int s = rem >> 6, d = rem & 63, b = bh / kH, h = bh % kH;
    size_t dst = ((size_t)(b * kS + s) << 10) + (h << 6) + d;
    split2(o[idx], oh + dst, ol + dst);
}

__global__ void split_k(const float* __restrict__ x, __half* __restrict__ h, __half* __restrict__ l)
{
    int i = blockIdx.x * blockDim.x + threadIdx.x;
    split2(x[i], h + i, l + i);
}

__global__ void rmsnorm_k(const float* __restrict__ x, const float* __restrict__ w,
                          __half* __restrict__ yh, __half* __restrict__ yl)
{
    const int r = blockIdx.x, t = threadIdx.x;
    const float* xr = x + (size_t)r * kE;
    __shared__ float red[256];
    float sum = 0.f;
    for (int i = t; i < kE; i += 256) { float v = xr[i]; sum += v * v; }
    red[t] = sum; __syncthreads();
    for (int o = 128; o > 0; o >>= 1) { if (t < o) red[t] += red[t+o]; __syncthreads(); }
    float rs = rsqrtf(red[0] / kE + 1.1920929e-7f);
    for (int i = t; i < kE; i += 256) {
        size_t o = (size_t)r * kE + i;
        split2(xr[i] * rs * w[i], yh + o, yl + o);
    }
}

__global__ void elumul_k(const float* __restrict__ u, const float* __restrict__ g,
                         __half* __restrict__ uh, __half* __restrict__ ul)
{
    int i = blockIdx.x * blockDim.x + threadIdx.x;
    float gv = g[i];
    split2(u[i] * (gv > 0.f ? gv : expm1f(gv)), uh + i, ul + i);
}

// ------------------------- host launcher -------------------------
#define SYM(p, s) cudaGetSymbolAddress((void**)&p, s)

extern "C" void kernel_launch(void* const* d_in, const int* in_sizes, int n_in,
                              void* d_out, int out_size)
{
    (void)in_sizes; (void)n_in; (void)out_size;
    const int*   tokens = (const int*)  d_in[0];
    const float* table = (const float*)d_in[1];
    const float *Wq = (const float*)d_in[2], *Wk = (const float*)d_in[3], *Wv = (const float*)d_in[4];
    const float *Wproj = (const float*)d_in[5], *normw = (const float*)d_in[6];
    const float *Wup = (const float*)d_in[7], *Wgate = (const float*)d_in[8], *Wdown = (const float*)d_in[9];
    const float *predW = (const float*)d_in[10], *predB = (const float*)d_in[11];
    float* logits = (float*)d_out;

    float *emb, *qkv, *sc, *o, *u, *g, *ct, *st;
    __half *eh, *el, *wqkvh, *wqkvl, *qh, *ql, *kh, *kl, *vth, *vtl, *ph, *pl;
    __half *o2h, *o2l, *wph, *wpl, *wuh, *wul, *wgh, *wgl, *wdh, *wdl, *hh, *hl, *uh, *ul, *pwh;
    SYM(emb, g_emb); SYM(qkv, g_qkv); SYM(sc, g_sc); SYM(o, g_o); SYM(u, g_u); SYM(g, g_g);
    SYM(ct, g_ct); SYM(st, g_st);
    SYM(eh, g_eh); SYM(el, g_el); SYM(wqkvh, g_wqkvh); SYM(wqkvl, g_wqkvl);
    SYM(qh, g_qh); SYM(ql, g_ql); SYM(kh, g_kh); SYM(kl, g_kl);
    SYM(vth, g_vth); SYM(vtl, g_vtl); SYM(ph, g_ph); SYM(pl, g_pl);
    SYM(o2h, g_o2h); SYM(o2l, g_o2l); SYM(wph, g_wph); SYM(wpl, g_wpl);
    SYM(wuh, g_wuh); SYM(wul, g_wul); SYM(wgh, g_wgh); SYM(wgl, g_wgl);
    SYM(wdh, g_wdh); SYM(wdl, g_wdl); SYM(hh, g_hh); SYM(hl, g_hl);
    SYM(uh, g_uh); SYM(ul, g_ul); SYM(pwh, g_pwh);

    const int SMS128 = 2 * 2 * (128 * 176 + 128 * 176);  // split BN=128: 180224
    const int SMS64  = 2 * 2 * (128 * 176 + 64 * 176);   // split BN=64:  135168
    const int SMU128 = 2 * (128 * 176 + 128 * 176);      // unsplit BN=128: 90112
    cudaFuncSetAttribute(tgemm_k<128,true ,false,false,false,false>, cudaFuncAttributeMaxDynamicSharedMemorySize, SMS128);
    cudaFuncSetAttribute(tgemm_k<128,true ,false,false,true ,false>, cudaFuncAttributeMaxDynamicSharedMemorySize, SMS128);
    cudaFuncSetAttribute(tgemm_k<128,true ,true ,false,false,false>, cudaFuncAttributeMaxDynamicSharedMemorySize, SMS128);
    cudaFuncSetAttribute(tgemm_k<64 ,true ,false,false,false,true >, cudaFuncAttributeMaxDynamicSharedMemorySize, SMS64);
    cudaFuncSetAttribute(tgemm_k<128,false,false,true ,false,false>, cudaFuncAttributeMaxDynamicSharedMemorySize, SMU128);

    embed_k <<<kBS * kE / 256, 256>>>(tokens, table, emb, eh, el);
    costab_k<<<kS * kD / 256, 256>>>(ct, st);

    for (int l = 0; l < 4; l++) {
        const float* wq = Wq    + (size_t)l * kH * kE * kD;
        const float* wk = Wk    + (size_t)l * kH * kE * kD;
        const float* wv = Wv    + (size_t)l * kH * kE * kD;
        const float* wp = Wproj + (size_t)l * kE * kE;
        const float* nw = normw + (size_t)l * kE;
        const float* wu = Wup   + (size_t)l * kE * kF;
        const float* wg = Wgate + (size_t)l * kE * kF;
        const float* wd = Wdown + (size_t)l * kF * kE;

        // QKV (split): [2048,1024] x [3072,1024]^T
        wqkv_k<<<kQKV * kE / 256, 256>>>(wq, wk, wv, wqkvh, wqkvl);
        tgemm_k<128,true,false,false,false,false><<<dim3(kQKV/128, kBS/128), 512, SMS128>>>(
            eh, el, kE, 0, wqkvh, wqkvl, kE, 0, qkv, kQKV, 0, nullptr, 1.f, kE);
        rope_k<<<kBS * kQKV / 256, 256>>>(qkv, ct, st, qh, ql, kh, kl, vth, vtl);

        // scores (split, causal tile-skip)
        tgemm_k<128,true,false,false,true,false><<<dim3(kS/128, kS/128, kBH), 512, SMS128>>>(
            qh, ql, kD, (long long)kS*kD, kh, kl, kD, (long long)kS*kD,
            sc, kS, (long long)kS*kS, nullptr, 0.125f, kD);
        softmax_k<<<kBH * kS, 256>>>(sc, ph, pl);

        // o = P @ V (split, causal K-bound)
        tgemm_k<64,true,false,false,false,true><<<dim3(1, kS/128, kBH), 512, SMS64>>>(
            ph, pl, kS, (long long)kS*kS, vth, vtl, kS, (long long)kD*kS,
            o, kD, (long long)kS*kD, nullptr, 1.f, kS);
        oresh_k<<<kBH * kS * kD / 256, 256>>>(o, o2h, o2l);

        // emb += o2 @ Wproj (split)
        wtr_k<<<dim3(kE/32, kE/32), dim3(32,8)>>>(wp, wph, wpl, kE, kE);
        tgemm_k<128,true,true,false,false,false><<<dim3(kE/128, kBS/128), 512, SMS128>>>(
            o2h, o2l, kE, 0, wph, wpl, kE, 0, emb, kE, 0, nullptr, 1.f, kE);

        // MLP (split)
        rmsnorm_k<<<kBS, 256>>>(emb, nw, hh, hl);
        wtr_k<<<dim3(kF/32, kE/32), dim3(32,8)>>>(wu, wuh, wul, kE, kF);
        wtr_k<<<dim3(kF/32, kE/32), dim3(32,8)>>>(wg, wgh, wgl, kE, kF);
        tgemm_k<128,true,false,false,false,false><<<dim3(kF/128, kBS/128), 512, SMS128>>>(
            hh, hl, kE, 0, wuh, wul, kE, 0, u, kF, 0, nullptr, 1.f, kE);
        tgemm_k<128,true,false,false,false,false><<<dim3(kF/128, kBS/128), 512, SMS128>>>(
            hh, hl, kE, 0, wgh, wgl, kE, 0, g, kF, 0, nullptr, 1.f, kE);
        elumul_k<<<kBS * kF / 256, 256>>>(u, g, uh, ul);
        wtr_k<<<dim3(kE/32, kF/32), dim3(32,8)>>>(wd, wdh, wdl, kF, kE);
        tgemm_k<128,true,true,false,false,false><<<dim3(kE/128, kBS/128), 512, SMS128>>>(
            uh, ul, kF, 0, wdh, wdl, kF, 0, emb, kE, 0, nullptr, 1.f, kF);
        split_k<<<kBS * kE / 256, 256>>>(emb, eh, el);
    }

    // logits (UNSPLIT fp16, fp32 acc) = emb @ predW + predB
    // error anchored at ~3e-4 (single terminal unsplit GEMM, R8 calibration)
    wtr_k<<<dim3(kV/32, kE/32), dim3(32,8)>>>(predW, pwh, nullptr, kE, kV);
    tgemm_k<128,false,false,true,false,false><<<dim3(kV/128, kBS/128), 512, SMU128>>>(
        eh, nullptr, kE, 0, pwh, nullptr, kE, 0, logits, kV, 0, predB, 1.f, kE);
}

// round 10
// speedup vs baseline: 3.0235x; 1.0932x over previous
#include <cuda_runtime.h>
#include <cuda_fp16.h>
#include <math.h>
#include <stdint.h>

namespace {
constexpr int kB = 2, kS = 1024, kE = 1024, kH = 16, kD = 64, kF = 4096, kV = 32000;
constexpr int kBS = kB * kS, kBH = kB * kH, kQKV = 3 * kE;
}

// ------------------------- device scratch -------------------------
__device__ float  g_emb [kBS * kE];
__device__ float  g_qkv [kBS * kQKV];
__device__ float  g_sc  [(size_t)kBH * kS * kS];
__device__ float  g_o   [kBH * kS * kD];
__device__ float  g_u   [kBS * kF];
__device__ float  g_g   [kBS * kF];
__device__ float  g_ct  [kS * kD];
__device__ float  g_st  [kS * kD];

__device__ __half g_eh[kBS*kE], g_el[kBS*kE];
__device__ __half g_wqkvh[kQKV*kE], g_wqkvl[kQKV*kE];
__device__ __half g_qh[kBH*kS*kD], g_ql[kBH*kS*kD];
__device__ __half g_kh[kBH*kS*kD], g_kl[kBH*kS*kD];
__device__ __half g_vth[kBH*kD*kS], g_vtl[kBH*kD*kS];
__device__ __half g_ph[(size_t)kBH*kS*kS], g_pl[(size_t)kBH*kS*kS];
__device__ __half g_o2h[kBS*kE], g_o2l[kBS*kE];
__device__ __half g_wph[kE*kE],  g_wpl[kE*kE];
__device__ __half g_wuh[kF*kE];
__device__ __half g_wgh[kF*kE];
__device__ __half g_wdh[kE*kF],  g_wdl[kE*kF];
__device__ __half g_hh[kBS*kE],  g_hl[kBS*kE];
__device__ __half g_uh[kBS*kF],  g_ul[kBS*kF];
__device__ __half g_pwh[(size_t)kV*kE];

// ------------------------- PTX helpers -------------------------
__device__ __forceinline__ uint32_t smem_u32(const void* p) {
    uint32_t a;
    asm("{ .reg .u64 t; cvta.to.shared.u64 t, %1; cvt.u32.u64 %0, t; }" : "=r"(a) : "l"(p));
    return a;
}
__device__ __forceinline__ void cpasync16(uint32_t dst, const void* src) {
    asm volatile("cp.async.cg.shared.global [%0], [%1], 16;" :: "r"(dst), "l"(src));
}
#define CP_COMMIT() asm volatile("cp.async.commit_group;" ::: "memory")
#define CP_WAIT0()  asm volatile("cp.async.wait_group 0;" ::: "memory")

__device__ __forceinline__ void ldsm4(uint32_t* r, uint32_t addr) {
    asm volatile("ldmatrix.sync.aligned.m8n8.x4.shared.b16 {%0,%1,%2,%3}, [%4];"
        : "=r"(r[0]), "=r"(r[1]), "=r"(r[2]), "=r"(r[3]) : "r"(addr));
}
__device__ __forceinline__ void hmma(float* c, const uint32_t* a, const uint32_t* b) {
    asm volatile("mma.sync.aligned.m16n8k16.row.col.f32.f16.f16.f32 "
        "{%0,%1,%2,%3}, {%4,%5,%6,%7}, {%8,%9}, {%0,%1,%2,%3};"
        : "+f"(c[0]), "+f"(c[1]), "+f"(c[2]), "+f"(c[3])
        : "r"(a[0]), "r"(a[1]), "r"(a[2]), "r"(a[3]), "r"(b[0]), "r"(b[1]));
}
__device__ __forceinline__ void hmma16(uint32_t* c, const uint32_t* a, const uint32_t* b) {
    asm volatile("mma.sync.aligned.m16n8k16.row.col.f16.f16.f16.f16 "
        "{%0,%1}, {%2,%3,%4,%5}, {%6,%7}, {%0,%1};"
        : "+r"(c[0]), "+r"(c[1])
        : "r"(a[0]), "r"(a[1]), "r"(a[2]), "r"(a[3]), "r"(b[0]), "r"(b[1]));
}
__device__ __forceinline__ void split2(float v, __half* h, __half* l) {
    __half hi = __float2half(v);
    *h = hi;
    *l = __float2half((v - __half2float(hi)) * 1024.f);
}

// stage one ROWS x 64 fp16 tile into 176B-padded smem rows (conflict-free ldsm)
template<int ROWS, int TPB>
__device__ __forceinline__ void stage_cp(uint32_t dst, const __half* __restrict__ src,
                                         long long ld, int k0, int tid)
{
#pragma unroll
    for (int it = 0; it < ROWS * 8 / TPB; it++) {
        int i = it * TPB + tid;
        int r = i >> 3, c = i & 7;
        cpasync16(dst + r * 176 + c * 16, src + (long long)r * ld + k0 + c * 8);
    }
}

// ------------------------- HMMA GEMM -------------------------
// C[M,N] = alpha * (A @ B^T) (+bias[n]) (+C).
// MODE 2 (full split): x = hi + lo/1024 both operands;
//        acc1 fp32 = Ah*Bh; acc2 fp16 = Ah*Bl + Al*Bh; C = acc1 + acc2/1024.
// MODE 1 (one-sided): A split, B hi only; acc2 = Al*Bh.
// MODE 0 (unsplit):   single fp16 operands, fp32 accumulate.
// BM=128, BK=64, 512 thr (4x4 warps, 32x32 warp tiles), 2-stage cp.async.
// CAUSAL: skip tiles above diagonal. CAUSK: clamp K at (by+1)*128.
template<int BN, int MODE, bool ACCUM, bool BIAS, bool CAUSAL, bool CAUSK>
__global__ void __launch_bounds__(512, 1)
tgemm_k(const __half* __restrict__ Ah, const __half* __restrict__ Al, int lda, long long sA,
        const __half* __restrict__ Bh, const __half* __restrict__ Bl, int ldb, long long sB,
        float* __restrict__ C, int ldc, long long sC,
        const float* __restrict__ bias, float alpha, int K)
{
    constexpr int BM = 128, BK = 64, TPB = 512;
    constexpr int WM = 4, WN = 4;
    constexpr int MT = BM / (WM * 16);
    constexpr int NT = BN / (WN * 8);
    constexpr int TILEA = BM * 176;
    constexpr int TILEB = BN * 176;
    constexpr int NA = (MODE >= 1) ? 2 : 1;
    constexpr int NB = (MODE == 2) ? 2 : 1;
    constexpr int STAGE = NA * TILEA + NB * TILEB;

    const int bx = blockIdx.x, by = blockIdx.y, bz = blockIdx.z;
    if (CAUSAL && bx * BN > by * BM + BM - 1) return;
    int Ktot = K;
    if (CAUSK) { int km = (by + 1) * BM; if (km < Ktot) Ktot = km; }
    const int NC = Ktot / BK;

    extern __shared__ char sm[];
    const uint32_t sb = smem_u32(sm);
    const int tid = threadIdx.x, lane = tid & 31, wid = tid >> 5;
    const int m0 = (wid / WN) * MT * 16;
    const int n0 = (wid % WN) * NT * 8;

    const __half* pAh = Ah + bz * sA + (long long)by * BM * lda;
    const __half* pAl = (MODE >= 1) ? Al + bz * sA + (long long)by * BM * lda : nullptr;
    const __half* pBh = Bh + bz * sB + (long long)bx * BN * ldb;
    const __half* pBl = (MODE == 2) ? Bl + bz * sB + (long long)bx * BN * ldb : nullptr;

    float    acc1[MT][NT][4];
    uint32_t acc2[MT][NT][2];
#pragma unroll
    for (int mt = 0; mt < MT; mt++)
#pragma unroll
        for (int nt = 0; nt < NT; nt++) {
#pragma unroll
            for (int i = 0; i < 4; i++) acc1[mt][nt][i] = 0.f;
            acc2[mt][nt][0] = 0u; acc2[mt][nt][1] = 0u;
        }

    auto stage_all = [&](int buf, int k0) {
        uint32_t s0 = sb + (uint32_t)buf * STAGE;
        stage_cp<BM, TPB>(s0, pAh, lda, k0, tid);
        stage_cp<BN, TPB>(s0 + NA*TILEA, pBh, ldb, k0, tid);
        if (MODE >= 1) stage_cp<BM, TPB>(s0 + TILEA, pAl, lda, k0, tid);
        if (MODE == 2) stage_cp<BN, TPB>(s0 + NA*TILEA + TILEB, pBl, ldb, k0, tid);
    };

    stage_all(0, 0); CP_COMMIT();

    for (int i = 0; i < NC; i++) {
        CP_WAIT0();
        __syncthreads();
        if (i + 1 < NC) { stage_all((i + 1) & 1, (i + 1) * BK); CP_COMMIT(); }

        const uint32_t s0 = sb + (uint32_t)(i & 1) * STAGE;
        const uint32_t aH = s0, aL = s0 + TILEA;
        const uint32_t bH = s0 + NA*TILEA, bL = s0 + NA*TILEA + TILEB;

#pragma unroll
        for (int ks = 0; ks < 4; ks++) {
            const int kc = ks * 2;
            uint32_t ah[MT][4], al[MT][4], bhf[NT][2], blf[NT][2];

#pragma unroll
            for (int nt = 0; nt < NT; nt += 2) {
                const int g = lane >> 3;
                const uint32_t off =
                    (uint32_t)(n0 + nt * 8 + ((g >> 1) << 3) + (lane & 7)) * 176
                    + (uint32_t)(kc + (g & 1)) * 16;
                uint32_t r[4];
                ldsm4(r, bH + off);
                bhf[nt][0] = r[0]; bhf[nt][1] = r[1];
                bhf[nt+1][0] = r[2]; bhf[nt+1][1] = r[3];
                if (MODE == 2) {
                    ldsm4(r, bL + off);
                    blf[nt][0] = r[0]; blf[nt][1] = r[1];
                    blf[nt+1][0] = r[2]; blf[nt+1][1] = r[3];
                }
            }
#pragma unroll
            for (int mt = 0; mt < MT; mt++) {
                const uint32_t off =
                    (uint32_t)(m0 + mt * 16 + (lane & 15)) * 176
                    + (uint32_t)(kc + (lane >> 4)) * 16;
                ldsm4(ah[mt], aH + off);
                if (MODE >= 1) ldsm4(al[mt], aL + off);
            }
#pragma unroll
            for (int mt = 0; mt < MT; mt++)
#pragma unroll
                for (int nt = 0; nt < NT; nt++) {
                    hmma(acc1[mt][nt], ah[mt], bhf[nt]);
                    if (MODE == 2) hmma16(acc2[mt][nt], ah[mt], blf[nt]);
                    if (MODE >= 1) hmma16(acc2[mt][nt], al[mt], bhf[nt]);
                }
        }
    }

    // ---- epilogue ----
    const float inv = 1.f / 1024.f;
    float* Cp = C + bz * sC;
#pragma unroll
    for (int mt = 0; mt < MT; mt++) {
#pragma unroll
        for (int nt = 0; nt < NT; nt++) {
            const int row = by * BM + m0 + mt * 16 + (lane >> 2);
            const int col = bx * BN + n0 + nt * 8 + ((lane & 3) << 1);
#pragma unroll
            for (int h = 0; h < 2; h++) {
                const int r = row + h * 8;
                float v0 = acc1[mt][nt][2*h], v1 = acc1[mt][nt][2*h+1];
                if (MODE >= 1) {
                    __half2 c2 = *reinterpret_cast<__half2*>(&acc2[mt][nt][h]);
                    v0 += __low2float(c2) * inv;
                    v1 += __high2float(c2) * inv;
                }
                v0 *= alpha; v1 *= alpha;
                if (BIAS) { v0 += bias[col]; v1 += bias[col + 1]; }
                float2* p = reinterpret_cast<float2*>(Cp + (long long)r * ldc + col);
                if (ACCUM) { float2 o = *p; v0 += o.x; v1 += o.y; }
                *p = make_float2(v0, v1);
            }
        }
    }
}

// ------------------------- elementwise kernels -------------------------
__global__ void embed_k(const int* __restrict__ tok, const float* __restrict__ tab,
                        float* __restrict__ out, __half* __restrict__ eh, __half* __restrict__ el)
{
    int idx = blockIdx.x * blockDim.x + threadIdx.x;
    float v = tab[(size_t)tok[idx >> 10] * kE + (idx & 1023)];
    out[idx] = v; split2(v, eh + idx, el + idx);
}

__global__ void costab_k(float* __restrict__ ct, float* __restrict__ st)
{
    int idx = blockIdx.x * blockDim.x + threadIdx.x;
    int s = idx / kD, i = idx % kD;
    float theta = powf(10000.f, (-2.f / kD) * (float)(i & 31));
    ct[idx] = cosf((float)s * theta);
    st[idx] = sinf((float)s * theta) * (i < kD/2 ? -1.f : 1.f);
}

__global__ void wqkv_k(const float* __restrict__ wq, const float* __restrict__ wk,
                       const float* __restrict__ wv, __half* __restrict__ h, __half* __restrict__ l)
{
    int idx = blockIdx.x * blockDim.x + threadIdx.x;
    int n = idx / kE, e = idx % kE;
    int seg = n >> 10, hh = (n & 1023) >> 6, k = n & 63;
    const float* w = seg == 0 ? wq : seg == 1 ? wk : wv;
    split2(w[((size_t)hh * kE + e) * kD + k], h + idx, l + idx);
}

// src [K,N] fp32 -> dst [N,K] fp16 hi (and lo if dl != nullptr)
__global__ void wtr_k(const float* __restrict__ src, __half* __restrict__ dh,
                      __half* __restrict__ dl, int K, int N)
{
    __shared__ float t[32][33];
    int k0 = blockIdx.y * 32, n0 = blockIdx.x * 32;
    for (int r = threadIdx.y; r < 32; r += 8)
        t[r][threadIdx.x] = src[(size_t)(k0 + r) * N + n0 + threadIdx.x];
    __syncthreads();
    for (int r = threadIdx.y; r < 32; r += 8) {
        size_t o = (size_t)(n0 + r) * K + k0 + threadIdx.x;
        float v = t[threadIdx.x][r];
        if (dl) split2(v, dh + o, dl + o);
        else    dh[o] = __float2half(v);
    }
}

__global__ void rope_k(const float* __restrict__ qkv, const float* __restrict__ ct,
                       const float* __restrict__ st,
                       __half* __restrict__ qh, __half* __restrict__ ql,
                       __half* __restrict__ kh, __half* __restrict__ kl,
                       __half* __restrict__ vth, __half* __restrict__ vtl)
{
    int idx = blockIdx.x * blockDim.x + threadIdx.x;
    int row = idx / kQKV, c = idx % kQKV;
    int b = row >> 10, s = row & 1023;
    int seg = c >> 10, h = (c & 1023) >> 6, i = c & 63;
    float x = qkv[idx];
    if (seg == 2) {
        size_t dst = ((size_t)(b * kH + h) * kD + i) * kS + s;
        split2(x, vth + dst, vtl + dst);
        return;
    }
    float sw = qkv[(size_t)row * kQKV + (seg << 10) + (h << 6) + ((i + 32) & 63)];
    float val = ct[(s << 6) + i] * x + st[(s << 6) + i] * sw;
    size_t dst = ((size_t)(b * kH + h) * kS + s) * kD + i;
    if (seg == 0) split2(val, qh + dst, ql + dst);
    else          split2(val, kh + dst, kl + dst);
}

// register-resident causal softmax: 256 threads, 4 cols/thread
__global__ void softmax_k(const float* __restrict__ sc,
                          __half* __restrict__ ph, __half* __restrict__ pl)
{
    const int r = blockIdx.x, s = r & (kS - 1), n = s + 1, t = threadIdx.x;
    const float* row = sc + (size_t)r * kS;
    __half* prh = ph + (size_t)r * kS;
    __half* prl = pl + (size_t)r * kS;
    __shared__ float red[256];

    float v[4];
#pragma unroll
    for (int j = 0; j < 4; j++) {
        int i = t + j * 256;
        v[j] = (i < n) ? row[i] : -INFINITY;
    }
    float m = fmaxf(fmaxf(v[0], v[1]), fmaxf(v[2], v[3]));
    red[t] = m; __syncthreads();
    for (int o = 128; o > 0; o >>= 1) { if (t < o) red[t] = fmaxf(red[t], red[t+o]); __syncthreads(); }
    m = red[0]; __syncthreads();

    float e[4], sum = 0.f;
#pragma unroll
    for (int j = 0; j < 4; j++) {
        int i = t + j * 256;
        e[j] = (i < n) ? expf(v[j] - m) : 0.f;
        sum += e[j];
    }
    red[t] = sum; __syncthreads();
    for (int o = 128; o > 0; o >>= 1) { if (t < o) red[t] += red[t+o]; __syncthreads(); }
    float inv = 1.f / red[0];
#pragma unroll
    for (int j = 0; j < 4; j++) {
        int i = t + j * 256;
        split2(e[j] * inv, prh + i, prl + i);
    }
}

__global__ void oresh_k(const float* __restrict__ o, __half* __restrict__ oh, __half* __restrict__ ol)
{
    int idx = blockIdx.x * blockDim.x + threadIdx.x;
    int bh = idx / (kS * kD), rem = idx % (kS * kD);
    int s = rem >> 6, d = rem & 63, b = bh / kH, h = bh % kH;
    size_t dst = ((size_t)(b * kS + s) << 10) + (h << 6) + d;
    split2(o[idx], oh + dst, ol + dst);
}

__global__ void split_k(const float* __restrict__ x, __half* __restrict__ h, __half* __restrict__ l)
{
    int i = blockIdx.x * blockDim.x + threadIdx.x;
    split2(x[i], h + i, l + i);
}

__global__ void rmsnorm_k(const float* __restrict__ x, const float* __restrict__ w,
                          __half* __restrict__ yh, __half* __restrict__ yl)
{
    const int r = blockIdx.x, t = threadIdx.x;
    const float* xr = x + (size_t)r * kE;
    __shared__ float red[256];
    float sum = 0.f;
    for (int i = t; i < kE; i += 256) { float v = xr[i]; sum += v * v; }
    red[t] = sum; __syncthreads();
    for (int o = 128; o > 0; o >>= 1) { if (t < o) red[t] += red[t+o]; __syncthreads(); }
    float rs = rsqrtf(red[0] / kE + 1.1920929e-7f);
    for (int i = t; i < kE; i += 256) {
        size_t o = (size_t)r * kE + i;
        split2(xr[i] * rs * w[i], yh + o, yl + o);
    }
}

__global__ void elumul_k(const float* __restrict__ u, const float* __restrict__ g,
                         __half* __restrict__ uh, __half* __restrict__ ul)
{
    int i = blockIdx.x * blockDim.x + threadIdx.x;
    float gv = g[i];
    split2(u[i] * (gv > 0.f ? gv : expm1f(gv)), uh + i, ul + i);
}

// ------------------------- host launcher -------------------------
#define SYM(p, s) cudaGetSymbolAddress((void**)&p, s)

extern "C" void kernel_launch(void* const* d_in, const int* in_sizes, int n_in,
                              void* d_out, int out_size)
{
    (void)in_sizes; (void)n_in; (void)out_size;
    const int*   tokens = (const int*)  d_in[0];
    const float* table = (const float*)d_in[1];
    const float *Wq = (const float*)d_in[2], *Wk = (const float*)d_in[3], *Wv = (const float*)d_in[4];
    const float *Wproj = (const float*)d_in[5], *normw = (const float*)d_in[6];
    const float *Wup = (const float*)d_in[7], *Wgate = (const float*)d_in[8], *Wdown = (const float*)d_in[9];
    const float *predW = (const float*)d_in[10], *predB = (const float*)d_in[11];
    float* logits = (float*)d_out;

    float *emb, *qkv, *sc, *o, *u, *g, *ct, *st;
    __half *eh, *el, *wqkvh, *wqkvl, *qh, *ql, *kh, *kl, *vth, *vtl, *ph, *pl;
    __half *o2h, *o2l, *wph, *wpl, *wuh, *wgh, *wdh, *wdl, *hh, *hl, *uh, *ul, *pwh;
    SYM(emb, g_emb); SYM(qkv, g_qkv); SYM(sc, g_sc); SYM(o, g_o); SYM(u, g_u); SYM(g, g_g);
    SYM(ct, g_ct); SYM(st, g_st);
    SYM(eh, g_eh); SYM(el, g_el); SYM(wqkvh, g_wqkvh); SYM(wqkvl, g_wqkvl);
    SYM(qh, g_qh); SYM(ql, g_ql); SYM(kh, g_kh); SYM(kl, g_kl);
    SYM(vth, g_vth); SYM(vtl, g_vtl); SYM(ph, g_ph); SYM(pl, g_pl);
    SYM(o2h, g_o2h); SYM(o2l, g_o2l); SYM(wph, g_wph); SYM(wpl, g_wpl);
    SYM(wuh, g_wuh); SYM(wgh, g_wgh); SYM(wdh, g_wdh); SYM(wdl, g_wdl);
    SYM(hh, g_hh); SYM(hl, g_hl); SYM(uh, g_uh); SYM(ul, g_ul); SYM(pwh, g_pwh);

    const int SMS128 = 2 * 2 * (128 * 176 + 128 * 176);   // MODE2 BN=128: 180224
    const int SMS64  = 2 * 2 * (128 * 176 + 64 * 176);    // MODE2 BN=64:  135168
    const int SM1128 = 2 * (2 * 128 * 176 + 128 * 176);   // MODE1 BN=128: 135168
    const int SMU128 = 2 * (128 * 176 + 128 * 176);       // MODE0 BN=128: 90112
    cudaFuncSetAttribute(tgemm_k<128,2,false,false,false,false>, cudaFuncAttributeMaxDynamicSharedMemorySize, SMS128);
    cudaFuncSetAttribute(tgemm_k<128,2,false,false,true ,false>, cudaFuncAttributeMaxDynamicSharedMemorySize, SMS128);
    cudaFuncSetAttribute(tgemm_k<128,2,true ,false,false,false>, cudaFuncAttributeMaxDynamicSharedMemorySize, SMS128);
    cudaFuncSetAttribute(tgemm_k<64 ,2,false,false,false,true >, cudaFuncAttributeMaxDynamicSharedMemorySize, SMS64);
    cudaFuncSetAttribute(tgemm_k<128,1,false,false,false,false>, cudaFuncAttributeMaxDynamicSharedMemorySize, SM1128);
    cudaFuncSetAttribute(tgemm_k<128,0,false,true ,false,false>, cudaFuncAttributeMaxDynamicSharedMemorySize, SMU128);

    embed_k <<<kBS * kE / 256, 256>>>(tokens, table, emb, eh, el);
    costab_k<<<kS * kD / 256, 256>>>(ct, st);

    for (int l = 0; l < 4; l++) {
        const float* wq = Wq    + (size_t)l * kH * kE * kD;
        const float* wk = Wk    + (size_t)l * kH * kE * kD;
        const float* wv = Wv    + (size_t)l * kH * kE * kD;
        const float* wp = Wproj + (size_t)l * kE * kE;
        const float* nw = normw + (size_t)l * kE;
        const float* wu = Wup   + (size_t)l * kE * kF;
        const float* wg = Wgate + (size_t)l * kE * kF;
        const float* wd = Wdown + (size_t)l * kF * kE;

        // QKV (full split): [2048,1024] x [3072,1024]^T
        wqkv_k<<<kQKV * kE / 256, 256>>>(wq, wk, wv, wqkvh, wqkvl);
        tgemm_k<128,2,false,false,false,false><<<dim3(kQKV/128, kBS/128), 512, SMS128>>>(
            eh, el, kE, 0, wqkvh, wqkvl, kE, 0, qkv, kQKV, 0, nullptr, 1.f, kE);
        rope_k<<<kBS * kQKV / 256, 256>>>(qkv, ct, st, qh, ql, kh, kl, vth, vtl);

        // scores (full split, causal tile-skip)
        tgemm_k<128,2,false,false,true,false><<<dim3(kS/128, kS/128, kBH), 512, SMS128>>>(
            qh, ql, kD, (long long)kS*kD, kh, kl, kD, (long long)kS*kD,
            sc, kS, (long long)kS*kS, nullptr, 0.125f, kD);
        softmax_k<<<kBH * kS, 256>>>(sc, ph, pl);

        // o = P @ V (full split, causal K-bound)
        tgemm_k<64,2,false,false,false,true><<<dim3(1, kS/128, kBH), 512, SMS64>>>(
            ph, pl, kS, (long long)kS*kS, vth, vtl, kS, (long long)kD*kS,
            o, kD, (long long)kS*kD, nullptr, 1.f, kS);
        oresh_k<<<kBH * kS * kD / 256, 256>>>(o, o2h, o2l);

        // emb += o2 @ Wproj (full split)
        wtr_k<<<dim3(kE/32, kE/32), dim3(32,8)>>>(wp, wph, wpl, kE, kE);
        tgemm_k<128,2,true,false,false,false><<<dim3(kE/128, kBS/128), 512, SMS128>>>(
            o2h, o2l, kE, 0, wph, wpl, kE, 0, emb, kE, 0, nullptr, 1.f, kE);

        // MLP: up/gate ONE-SIDED (act split, weight fp16); down full split
        rmsnorm_k<<<kBS, 256>>>(emb, nw, hh, hl);
        wtr_k<<<dim3(kF/32, kE/32), dim3(32,8)>>>(wu, wuh, nullptr, kE, kF);
        wtr_k<<<dim3(kF/32, kE/32), dim3(32,8)>>>(wg, wgh, nullptr, kE, kF);
        tgemm_k<128,1,false,false,false,false><<<dim3(kF/128, kBS/128), 512, SM1128>>>(
            hh, hl, kE, 0, wuh, nullptr, kE, 0, u, kF, 0, nullptr, 1.f, kE);
        tgemm_k<128,1,false,false,false,false><<<dim3(kF/128, kBS/128), 512, SM1128>>>(
            hh, hl, kE, 0, wgh, nullptr, kE, 0, g, kF, 0, nullptr, 1.f, kE);
        elumul_k<<<kBS * kF / 256, 256>>>(u, g, uh, ul);
        wtr_k<<<dim3(kE/32, kF/32), dim3(32,8)>>>(wd, wdh, wdl, kF, kE);
        tgemm_k<128,2,true,false,false,false><<<dim3(kE/128, kBS/128), 512, SMS128>>>(
            uh, ul, kF, 0, wdh, wdl, kF, 0, emb, kE, 0, nullptr, 1.f, kF);
        split_k<<<kBS * kE / 256, 256>>>(emb, eh, el);
    }

    // logits (UNSPLIT fp16, fp32 acc) = emb @ predW + predB
    wtr_k<<<dim3(kV/32, kE/32), dim3(32,8)>>>(predW, pwh, nullptr, kE, kV);
    tgemm_k<128,0,false,true,false,false><<<dim3(kV/128, kBS/128), 512, SMU128>>>(
        eh, nullptr, kE, 0, pwh, nullptr, kE, 0, logits, kV, 0, predB, 1.f, kE);
}

// round 11
// speedup vs baseline: 3.1798x; 1.0517x over previous
#include <cuda_runtime.h>
#include <cuda_fp16.h>
#include <math.h>
#include <stdint.h>

namespace {
constexpr int kB = 2, kS = 1024, kE = 1024, kH = 16, kD = 64, kF = 4096, kV = 32000;
constexpr int kBS = kB * kS, kBH = kB * kH, kQKV = 3 * kE;
}

// ------------------------- device scratch -------------------------
__device__ float  g_emb [kBS * kE];
__device__ float  g_qkv [kBS * kQKV];
__device__ float  g_sc  [(size_t)kBH * kS * kS];
__device__ float  g_o   [kBH * kS * kD];
__device__ float  g_u   [kBS * kF];
__device__ float  g_g   [kBS * kF];
__device__ float  g_ct  [kS * kD];
__device__ float  g_st  [kS * kD];

__device__ __half g_eh[kBS*kE], g_el[kBS*kE];
__device__ __half g_wqkvh[kQKV*kE], g_wqkvl[kQKV*kE];
__device__ __half g_qh[kBH*kS*kD], g_ql[kBH*kS*kD];
__device__ __half g_kh[kBH*kS*kD], g_kl[kBH*kS*kD];
__device__ __half g_vth[kBH*kD*kS], g_vtl[kBH*kD*kS];
__device__ __half g_ph[(size_t)kBH*kS*kS], g_pl[(size_t)kBH*kS*kS];
__device__ __half g_o2h[kBS*kE], g_o2l[kBS*kE];
__device__ __half g_wph[kE*kE],  g_wpl[kE*kE];
__device__ __half g_wuh[kF*kE];
__device__ __half g_wgh[kF*kE];
__device__ __half g_wdh[kE*kF];
__device__ __half g_hh[kBS*kE],  g_hl[kBS*kE];
__device__ __half g_uh[kBS*kF],  g_ul[kBS*kF];
__device__ __half g_pwh[(size_t)kV*kE];

// ------------------------- PTX helpers -------------------------
__device__ __forceinline__ uint32_t smem_u32(const void* p) {
    uint32_t a;
    asm("{ .reg .u64 t; cvta.to.shared.u64 t, %1; cvt.u32.u64 %0, t; }" : "=r"(a) : "l"(p));
    return a;
}
__device__ __forceinline__ void cpasync16(uint32_t dst, const void* src) {
    asm volatile("cp.async.cg.shared.global [%0], [%1], 16;" :: "r"(dst), "l"(src));
}
#define CP_COMMIT() asm volatile("cp.async.commit_group;" ::: "memory")
#define CP_WAIT0()  asm volatile("cp.async.wait_group 0;" ::: "memory")

__device__ __forceinline__ void ldsm4(uint32_t* r, uint32_t addr) {
    asm volatile("ldmatrix.sync.aligned.m8n8.x4.shared.b16 {%0,%1,%2,%3}, [%4];"
        : "=r"(r[0]), "=r"(r[1]), "=r"(r[2]), "=r"(r[3]) : "r"(addr));
}
__device__ __forceinline__ void hmma(float* c, const uint32_t* a, const uint32_t* b) {
    asm volatile("mma.sync.aligned.m16n8k16.row.col.f32.f16.f16.f32 "
        "{%0,%1,%2,%3}, {%4,%5,%6,%7}, {%8,%9}, {%0,%1,%2,%3};"
        : "+f"(c[0]), "+f"(c[1]), "+f"(c[2]), "+f"(c[3])
        : "r"(a[0]), "r"(a[1]), "r"(a[2]), "r"(a[3]), "r"(b[0]), "r"(b[1]));
}
__device__ __forceinline__ void hmma16(uint32_t* c, const uint32_t* a, const uint32_t* b) {
    asm volatile("mma.sync.aligned.m16n8k16.row.col.f16.f16.f16.f16 "
        "{%0,%1}, {%2,%3,%4,%5}, {%6,%7}, {%0,%1};"
        : "+r"(c[0]), "+r"(c[1])
        : "r"(a[0]), "r"(a[1]), "r"(a[2]), "r"(a[3]), "r"(b[0]), "r"(b[1]));
}
__device__ __forceinline__ void split2(float v, __half* h, __half* l) {
    __half hi = __float2half(v);
    *h = hi;
    *l = __float2half((v - __half2float(hi)) * 1024.f);
}

// stage one ROWS x 64 fp16 tile into 176B-padded smem rows (conflict-free ldsm)
template<int ROWS, int TPB>
__device__ __forceinline__ void stage_cp(uint32_t dst, const __half* __restrict__ src,
                                         long long ld, int k0, int tid)
{
#pragma unroll
    for (int it = 0; it < ROWS * 8 / TPB; it++) {
        int i = it * TPB + tid;
        int r = i >> 3, c = i & 7;
        cpasync16(dst + r * 176 + c * 16, src + (long long)r * ld + k0 + c * 8);
    }
}

// ------------------------- HMMA GEMM -------------------------
// C[M,N] = alpha * (A @ B^T) (+bias[n]) (+C).
// MODE 2 (full split): x = hi + lo/1024 both operands;
//        acc1 fp32 = Ah*Bh; acc2 fp16 = Ah*Bl + Al*Bh; C = acc1 + acc2/1024.
// MODE 1 (one-sided): A split, B hi only; acc2 = Al*Bh.
// MODE 0 (unsplit):   single fp16 operands, fp32 accumulate.
// BM=128, BK=64, 512 thr (4x4 warps, 32x32 warp tiles), 2-stage cp.async.
// CAUSAL: skip tiles above diagonal. CAUSK: clamp K at (by+1)*128.
template<int BN, int MODE, bool ACCUM, bool BIAS, bool CAUSAL, bool CAUSK>
__global__ void __launch_bounds__(512, 1)
tgemm_k(const __half* __restrict__ Ah, const __half* __restrict__ Al, int lda, long long sA,
        const __half* __restrict__ Bh, const __half* __restrict__ Bl, int ldb, long long sB,
        float* __restrict__ C, int ldc, long long sC,
        const float* __restrict__ bias, float alpha, int K)
{
    constexpr int BM = 128, BK = 64, TPB = 512;
    constexpr int WM = 4, WN = 4;
    constexpr int MT = BM / (WM * 16);
    constexpr int NT = BN / (WN * 8);
    constexpr int TILEA = BM * 176;
    constexpr int TILEB = BN * 176;
    constexpr int NA = (MODE >= 1) ? 2 : 1;
    constexpr int NB = (MODE == 2) ? 2 : 1;
    constexpr int STAGE = NA * TILEA + NB * TILEB;

    const int bx = blockIdx.x, by = blockIdx.y, bz = blockIdx.z;
    if (CAUSAL && bx * BN > by * BM + BM - 1) return;
    int Ktot = K;
    if (CAUSK) { int km = (by + 1) * BM; if (km < Ktot) Ktot = km; }
    const int NC = Ktot / BK;

    extern __shared__ char sm[];
    const uint32_t sb = smem_u32(sm);
    const int tid = threadIdx.x, lane = tid & 31, wid = tid >> 5;
    const int m0 = (wid / WN) * MT * 16;
    const int n0 = (wid % WN) * NT * 8;

    const __half* pAh = Ah + bz * sA + (long long)by * BM * lda;
    const __half* pAl = (MODE >= 1) ? Al + bz * sA + (long long)by * BM * lda : nullptr;
    const __half* pBh = Bh + bz * sB + (long long)bx * BN * ldb;
    const __half* pBl = (MODE == 2) ? Bl + bz * sB + (long long)bx * BN * ldb : nullptr;

    float    acc1[MT][NT][4];
    uint32_t acc2[MT][NT][2];
#pragma unroll
    for (int mt = 0; mt < MT; mt++)
#pragma unroll
        for (int nt = 0; nt < NT; nt++) {
#pragma unroll
            for (int i = 0; i < 4; i++) acc1[mt][nt][i] = 0.f;
            acc2[mt][nt][0] = 0u; acc2[mt][nt][1] = 0u;
        }

    auto stage_all = [&](int buf, int k0) {
        uint32_t s0 = sb + (uint32_t)buf * STAGE;
        stage_cp<BM, TPB>(s0, pAh, lda, k0, tid);
        stage_cp<BN, TPB>(s0 + NA*TILEA, pBh, ldb, k0, tid);
        if (MODE >= 1) stage_cp<BM, TPB>(s0 + TILEA, pAl, lda, k0, tid);
        if (MODE == 2) stage_cp<BN, TPB>(s0 + NA*TILEA + TILEB, pBl, ldb, k0, tid);
    };

    stage_all(0, 0); CP_COMMIT();

    for (int i = 0; i < NC; i++) {
        CP_WAIT0();
        __syncthreads();
        if (i + 1 < NC) { stage_all((i + 1) & 1, (i + 1) * BK); CP_COMMIT(); }

        const uint32_t s0 = sb + (uint32_t)(i & 1) * STAGE;
        const uint32_t aH = s0, aL = s0 + TILEA;
        const uint32_t bH = s0 + NA*TILEA, bL = s0 + NA*TILEA + TILEB;

#pragma unroll
        for (int ks = 0; ks < 4; ks++) {
            const int kc = ks * 2;
            uint32_t ah[MT][4], al[MT][4], bhf[NT][2], blf[NT][2];

#pragma unroll
            for (int nt = 0; nt < NT; nt += 2) {
                const int g = lane >> 3;
                const uint32_t off =
                    (uint32_t)(n0 + nt * 8 + ((g >> 1) << 3) + (lane & 7)) * 176
                    + (uint32_t)(kc + (g & 1)) * 16;
                uint32_t r[4];
                ldsm4(r, bH + off);
                bhf[nt][0] = r[0]; bhf[nt][1] = r[1];
                bhf[nt+1][0] = r[2]; bhf[nt+1][1] = r[3];
                if (MODE == 2) {
                    ldsm4(r, bL + off);
                    blf[nt][0] = r[0]; blf[nt][1] = r[1];
                    blf[nt+1][0] = r[2]; blf[nt+1][1] = r[3];
                }
            }
#pragma unroll
            for (int mt = 0; mt < MT; mt++) {
                const uint32_t off =
                    (uint32_t)(m0 + mt * 16 + (lane & 15)) * 176
                    + (uint32_t)(kc + (lane >> 4)) * 16;
                ldsm4(ah[mt], aH + off);
                if (MODE >= 1) ldsm4(al[mt], aL + off);
            }
#pragma unroll
            for (int mt = 0; mt < MT; mt++)
#pragma unroll
                for (int nt = 0; nt < NT; nt++) {
                    hmma(acc1[mt][nt], ah[mt], bhf[nt]);
                    if (MODE == 2) hmma16(acc2[mt][nt], ah[mt], blf[nt]);
                    if (MODE >= 1) hmma16(acc2[mt][nt], al[mt], bhf[nt]);
                }
        }
    }

    // ---- epilogue ----
    const float inv = 1.f / 1024.f;
    float* Cp = C + bz * sC;
#pragma unroll
    for (int mt = 0; mt < MT; mt++) {
#pragma unroll
        for (int nt = 0; nt < NT; nt++) {
            const int row = by * BM + m0 + mt * 16 + (lane >> 2);
            const int col = bx * BN + n0 + nt * 8 + ((lane & 3) << 1);
#pragma unroll
            for (int h = 0; h < 2; h++) {
                const int r = row + h * 8;
                float v0 = acc1[mt][nt][2*h], v1 = acc1[mt][nt][2*h+1];
                if (MODE >= 1) {
                    __half2 c2 = *reinterpret_cast<__half2*>(&acc2[mt][nt][h]);
                    v0 += __low2float(c2) * inv;
                    v1 += __high2float(c2) * inv;
                }
                v0 *= alpha; v1 *= alpha;
                if (BIAS) { v0 += bias[col]; v1 += bias[col + 1]; }
                float2* p = reinterpret_cast<float2*>(Cp + (long long)r * ldc + col);
                if (ACCUM) { float2 o = *p; v0 += o.x; v1 += o.y; }
                *p = make_float2(v0, v1);
            }
        }
    }
}

// ------------------------- elementwise kernels -------------------------
__global__ void embed_k(const int* __restrict__ tok, const float* __restrict__ tab,
                        float* __restrict__ out, __half* __restrict__ eh, __half* __restrict__ el)
{
    int idx = blockIdx.x * blockDim.x + threadIdx.x;
    float v = tab[(size_t)tok[idx >> 10] * kE + (idx & 1023)];
    out[idx] = v; split2(v, eh + idx, el + idx);
}

__global__ void costab_k(float* __restrict__ ct, float* __restrict__ st)
{
    int idx = blockIdx.x * blockDim.x + threadIdx.x;
    int s = idx / kD, i = idx % kD;
    float theta = powf(10000.f, (-2.f / kD) * (float)(i & 31));
    ct[idx] = cosf((float)s * theta);
    st[idx] = sinf((float)s * theta) * (i < kD/2 ? -1.f : 1.f);
}

__global__ void wqkv_k(const float* __restrict__ wq, const float* __restrict__ wk,
                       const float* __restrict__ wv, __half* __restrict__ h, __half* __restrict__ l)
{
    int idx = blockIdx.x * blockDim.x + threadIdx.x;
    int n = idx / kE, e = idx % kE;
    int seg = n >> 10, hh = (n & 1023) >> 6, k = n & 63;
    const float* w = seg == 0 ? wq : seg == 1 ? wk : wv;
    split2(w[((size_t)hh * kE + e) * kD + k], h + idx, l + idx);
}

// src [K,N] fp32 -> dst [N,K] fp16 hi (and lo if dl != nullptr)
__global__ void wtr_k(const float* __restrict__ src, __half* __restrict__ dh,
                      __half* __restrict__ dl, int K, int N)
{
    __shared__ float t[32][33];
    int k0 = blockIdx.y * 32, n0 = blockIdx.x * 32;
    for (int r = threadIdx.y; r < 32; r += 8)
        t[r][threadIdx.x] = src[(size_t)(k0 + r) * N + n0 + threadIdx.x];
    __syncthreads();
    for (int r = threadIdx.y; r < 32; r += 8) {
        size_t o = (size_t)(n0 + r) * K + k0 + threadIdx.x;
        float v = t[threadIdx.x][r];
        if (dl) split2(v, dh + o, dl + o);
        else    dh[o] = __float2half(v);
    }
}

__global__ void rope_k(const float* __restrict__ qkv, const float* __restrict__ ct,
                       const float* __restrict__ st,
                       __half* __restrict__ qh, __half* __restrict__ ql,
                       __half* __restrict__ kh, __half* __restrict__ kl,
                       __half* __restrict__ vth, __half* __restrict__ vtl)
{
    int idx = blockIdx.x * blockDim.x + threadIdx.x;
    int row = idx / kQKV, c = idx % kQKV;
    int b = row >> 10, s = row & 1023;
    int seg = c >> 10, h = (c & 1023) >> 6, i = c & 63;
    float x = qkv[idx];
    if (seg == 2) {
        size_t dst = ((size_t)(b * kH + h) * kD + i) * kS + s;
        split2(x, vth + dst, vtl + dst);
        return;
    }
    float sw = qkv[(size_t)row * kQKV + (seg << 10) + (h << 6) + ((i + 32) & 63)];
    float val = ct[(s << 6) + i] * x + st[(s << 6) + i] * sw;
    size_t dst = ((size_t)(b * kH + h) * kS + s) * kD + i;
    if (seg == 0) split2(val, qh + dst, ql + dst);
    else          split2(val, kh + dst, kl + dst);
}

// register-resident causal softmax; writes only cols < kend = ceil((s+1)/128)*128
// (PV clamps K at that boundary, so nothing beyond is ever read)
__global__ void softmax_k(const float* __restrict__ sc,
                          __half* __restrict__ ph, __half* __restrict__ pl)
{
    const int r = blockIdx.x, s = r & (kS - 1), n = s + 1, t = threadIdx.x;
    const int kend = ((s >> 7) + 1) << 7;
    const float* row = sc + (size_t)r * kS;
    __half* prh = ph + (size_t)r * kS;
    __half* prl = pl + (size_t)r * kS;
    __shared__ float red[256];

    float v[4];
#pragma unroll
    for (int j = 0; j < 4; j++) {
        int i = t + j * 256;
        v[j] = (i < n) ? row[i] : -INFINITY;
    }
    float m = fmaxf(fmaxf(v[0], v[1]), fmaxf(v[2], v[3]));
    red[t] = m; __syncthreads();
    for (int o = 128; o > 0; o >>= 1) { if (t < o) red[t] = fmaxf(red[t], red[t+o]); __syncthreads(); }
    m = red[0]; __syncthreads();

    float e[4], sum = 0.f;
#pragma unroll
    for (int j = 0; j < 4; j++) {
        int i = t + j * 256;
        e[j] = (i < n) ? expf(v[j] - m) : 0.f;
        sum += e[j];
    }
    red[t] = sum; __syncthreads();
    for (int o = 128; o > 0; o >>= 1) { if (t < o) red[t] += red[t+o]; __syncthreads(); }
    float inv = 1.f / red[0];
#pragma unroll
    for (int j = 0; j < 4; j++) {
        int i = t + j * 256;
        if (i < kend) split2(e[j] * inv, prh + i, prl + i);
    }
}

__global__ void oresh_k(const float* __restrict__ o, __half* __restrict__ oh, __half* __restrict__ ol)
{
    int idx = blockIdx.x * blockDim.x + threadIdx.x;
    int bh = idx / (kS * kD), rem = idx % (kS * kD);
    int s = rem >> 6, d = rem & 63, b = bh / kH, h = bh % kH;
    size_t dst = ((size_t)(b * kS + s) << 10) + (h << 6) + d;
    split2(o[idx], oh + dst, ol + dst);
}

__global__ void split_k(const float* __restrict__ x, __half* __restrict__ h, __half* __restrict__ l)
{
    int i = blockIdx.x * blockDim.x + threadIdx.x;
    split2(x[i], h + i, l + i);
}

__global__ void rmsnorm_k(const float* __restrict__ x, const float* __restrict__ w,
                          __half* __restrict__ yh, __half* __restrict__ yl)
{
    const int r = blockIdx.x, t = threadIdx.x;
    const float* xr = x + (size_t)r * kE;
    __shared__ float red[256];
    float sum = 0.f;
    for (int i = t; i < kE; i += 256) { float v = xr[i]; sum += v * v; }
    red[t] = sum; __syncthreads();
    for (int o = 128; o > 0; o >>= 1) { if (t < o) red[t] += red[t+o]; __syncthreads(); }
    float rs = rsqrtf(red[0] / kE + 1.1920929e-7f);
    for (int i = t; i < kE; i += 256) {
        size_t o = (size_t)r * kE + i;
        split2(xr[i] * rs * w[i], yh + o, yl + o);
    }
}

__global__ void elumul_k(const float* __restrict__ u, const float* __restrict__ g,
                         __half* __restrict__ uh, __half* __restrict__ ul)
{
    int i = blockIdx.x * blockDim.x + threadIdx.x;
    float gv = g[i];
    split2(u[i] * (gv > 0.f ? gv : expm1f(gv)), uh + i, ul + i);
}

// ------------------------- host launcher -------------------------
#define SYM(p, s) cudaGetSymbolAddress((void**)&p, s)

extern "C" void kernel_launch(void* const* d_in, const int* in_sizes, int n_in,
                              void* d_out, int out_size)
{
    (void)in_sizes; (void)n_in; (void)out_size;
    const int*   tokens = (const int*)  d_in[0];
    const float* table = (const float*)d_in[1];
    const float *Wq = (const float*)d_in[2], *Wk = (const float*)d_in[3], *Wv = (const float*)d_in[4];
    const float *Wproj = (const float*)d_in[5], *normw = (const float*)d_in[6];
    const float *Wup = (const float*)d_in[7], *Wgate = (const float*)d_in[8], *Wdown = (const float*)d_in[9];
    const float *predW = (const float*)d_in[10], *predB = (const float*)d_in[11];
    float* logits = (float*)d_out;

    float *emb, *qkv, *sc, *o, *u, *g, *ct, *st;
    __half *eh, *el, *wqkvh, *wqkvl, *qh, *ql, *kh, *kl, *vth, *vtl, *ph, *pl;
    __half *o2h, *o2l, *wph, *wpl, *wuh, *wgh, *wdh, *hh, *hl, *uh, *ul, *pwh;
    SYM(emb, g_emb); SYM(qkv, g_qkv); SYM(sc, g_sc); SYM(o, g_o); SYM(u, g_u); SYM(g, g_g);
    SYM(ct, g_ct); SYM(st, g_st);
    SYM(eh, g_eh); SYM(el, g_el); SYM(wqkvh, g_wqkvh); SYM(wqkvl, g_wqkvl);
    SYM(qh, g_qh); SYM(ql, g_ql); SYM(kh, g_kh); SYM(kl, g_kl);
    SYM(vth, g_vth); SYM(vtl, g_vtl); SYM(ph, g_ph); SYM(pl, g_pl);
    SYM(o2h, g_o2h); SYM(o2l, g_o2l); SYM(wph, g_wph); SYM(wpl, g_wpl);
    SYM(wuh, g_wuh); SYM(wgh, g_wgh); SYM(wdh, g_wdh);
    SYM(hh, g_hh); SYM(hl, g_hl); SYM(uh, g_uh); SYM(ul, g_ul); SYM(pwh, g_pwh);

    const int SMS128 = 2 * 2 * (128 * 176 + 128 * 176);   // MODE2 BN=128: 180224
    const int SMS64  = 2 * 2 * (128 * 176 + 64 * 176);    // MODE2 BN=64:  135168
    const int SM1128 = 2 * (2 * 128 * 176 + 128 * 176);   // MODE1 BN=128: 135168
    const int SMU128 = 2 * (128 * 176 + 128 * 176);       // MODE0 BN=128: 90112
    cudaFuncSetAttribute(tgemm_k<128,2,false,false,false,false>, cudaFuncAttributeMaxDynamicSharedMemorySize, SMS128);
    cudaFuncSetAttribute(tgemm_k<128,2,false,false,true ,false>, cudaFuncAttributeMaxDynamicSharedMemorySize, SMS128);
    cudaFuncSetAttribute(tgemm_k<128,2,true ,false,false,false>, cudaFuncAttributeMaxDynamicSharedMemorySize, SMS128);
    cudaFuncSetAttribute(tgemm_k<64 ,2,false,false,false,true >, cudaFuncAttributeMaxDynamicSharedMemorySize, SMS64);
    cudaFuncSetAttribute(tgemm_k<128,1,false,false,false,false>, cudaFuncAttributeMaxDynamicSharedMemorySize, SM1128);
    cudaFuncSetAttribute(tgemm_k<128,1,true ,false,false,false>, cudaFuncAttributeMaxDynamicSharedMemorySize, SM1128);
    cudaFuncSetAttribute(tgemm_k<128,0,false,true ,false,false>, cudaFuncAttributeMaxDynamicSharedMemorySize, SMU128);

    embed_k <<<kBS * kE / 256, 256>>>(tokens, table, emb, eh, el);
    costab_k<<<kS * kD / 256, 256>>>(ct, st);

    for (int l = 0; l < 4; l++) {
        const float* wq = Wq    + (size_t)l * kH * kE * kD;
        const float* wk = Wk    + (size_t)l * kH * kE * kD;
        const float* wv = Wv    + (size_t)l * kH * kE * kD;
        const float* wp = Wproj + (size_t)l * kE * kE;
        const float* nw = normw + (size_t)l * kE;
        const float* wu = Wup   + (size_t)l * kE * kF;
        const float* wg = Wgate + (size_t)l * kE * kF;
        const float* wd = Wdown + (size_t)l * kF * kE;

        // QKV (full split): [2048,1024] x [3072,1024]^T
        wqkv_k<<<kQKV * kE / 256, 256>>>(wq, wk, wv, wqkvh, wqkvl);
        tgemm_k<128,2,false,false,false,false><<<dim3(kQKV/128, kBS/128), 512, SMS128>>>(
            eh, el, kE, 0, wqkvh, wqkvl, kE, 0, qkv, kQKV, 0, nullptr, 1.f, kE);
        rope_k<<<kBS * kQKV / 256, 256>>>(qkv, ct, st, qh, ql, kh, kl, vth, vtl);

        // scores (full split, causal tile-skip)
        tgemm_k<128,2,false,false,true,false><<<dim3(kS/128, kS/128, kBH), 512, SMS128>>>(
            qh, ql, kD, (long long)kS*kD, kh, kl, kD, (long long)kS*kD,
            sc, kS, (long long)kS*kS, nullptr, 0.125f, kD);
        softmax_k<<<kBH * kS, 256>>>(sc, ph, pl);

        // o = P @ V (full split, causal K-bound)
        tgemm_k<64,2,false,false,false,true><<<dim3(1, kS/128, kBH), 512, SMS64>>>(
            ph, pl, kS, (long long)kS*kS, vth, vtl, kS, (long long)kD*kS,
            o, kD, (long long)kS*kD, nullptr, 1.f, kS);
        oresh_k<<<kBH * kS * kD / 256, 256>>>(o, o2h, o2l);

        // emb += o2 @ Wproj (full split)
        wtr_k<<<dim3(kE/32, kE/32), dim3(32,8)>>>(wp, wph, wpl, kE, kE);
        tgemm_k<128,2,true,false,false,false><<<dim3(kE/128, kBS/128), 512, SMS128>>>(
            o2h, o2l, kE, 0, wph, wpl, kE, 0, emb, kE, 0, nullptr, 1.f, kE);

        // MLP: up/gate/down ONE-SIDED (act split, weight fp16)
        rmsnorm_k<<<kBS, 256>>>(emb, nw, hh, hl);
        wtr_k<<<dim3(kF/32, kE/32), dim3(32,8)>>>(wu, wuh, nullptr, kE, kF);
        wtr_k<<<dim3(kF/32, kE/32), dim3(32,8)>>>(wg, wgh, nullptr, kE, kF);
        tgemm_k<128,1,false,false,false,false><<<dim3(kF/128, kBS/128), 512, SM1128>>>(
            hh, hl, kE, 0, wuh, nullptr, kE, 0, u, kF, 0, nullptr, 1.f, kE);
        tgemm_k<128,1,false,false,false,false><<<dim3(kF/128, kBS/128), 512, SM1128>>>(
            hh, hl, kE, 0, wgh, nullptr, kE, 0, g, kF, 0, nullptr, 1.f, kE);
        elumul_k<<<kBS * kF / 256, 256>>>(u, g, uh, ul);
        wtr_k<<<dim3(kE/32, kF/32), dim3(32,8)>>>(wd, wdh, nullptr, kF, kE);
        tgemm_k<128,1,true,false,false,false><<<dim3(kE/128, kBS/128), 512, SM1128>>>(
            uh, ul, kF, 0, wdh, nullptr, kF, 0, emb, kE, 0, nullptr, 1.f, kF);
        split_k<<<kBS * kE / 256, 256>>>(emb, eh, el);
    }

    // logits (UNSPLIT fp16, fp32 acc) = emb @ predW + predB
    wtr_k<<<dim3(kV/32, kE/32), dim3(32,8)>>>(predW, pwh, nullptr, kE, kV);
    tgemm_k<128,0,false,true,false,false><<<dim3(kV/128, kBS/128), 512, SMU128>>>(
        eh, nullptr, kE, 0, pwh, nullptr, kE, 0, logits, kV, 0, predB, 1.f, kE);
}